// round 1
// baseline (speedup 1.0000x reference)
#include <cuda_runtime.h>
#include <math.h>

// Problem dims (fixed by the dataset)
#define Bb   16
#define Nn   4096
#define Mm   1024
#define IDim 768
#define HDim 512
#define ODim 256
#define ROWS_IMG (Bb*Mm)   // 16384
#define ROWS_PT  (Bb*Nn)   // 65536

// ---------------- scratch (device globals; no allocation allowed) -------------
__device__ float g_xln[ROWS_IMG * IDim];            // 50 MB  : LN-normalized image tokens
__device__ float g_hbuf[ROWS_PT * HDim];            // 134 MB : hidden buffer (reused)
__device__ float g_imgfeat[ROWS_IMG * ODim];        // 17 MB  : image MLP output
__device__ float g_finln[ROWS_PT * (2 * ODim)];     // 134 MB : normalized fin (shared gate/delta)
__device__ float g_gate[ROWS_PT * ODim];            // 67 MB  : gate pre-sigmoid
__device__ int   g_knn_idx[ROWS_PT * 3];
__device__ float g_knn_w[ROWS_PT * 3];
__device__ float g_wp_ip[IDim * HDim];              // ln-folded weights
__device__ float g_wp_g[(2 * ODim) * HDim];
__device__ float g_wp_d[(2 * ODim) * HDim];
__device__ float g_bp_ip[HDim];
__device__ float g_bp_g[HDim];
__device__ float g_bp_d[HDim];

// ---------------- helpers ------------------------------------------------------
__device__ __forceinline__ float gelu_f(float x) {
    return 0.5f * x * (1.0f + erff(x * 0.70710678118654752f));
}
__device__ __forceinline__ float sigmoid_f(float x) {
    return 1.0f / (1.0f + __expf(-x));
}

// block-wide sum of (s, ss). Works for blockDim.x in {128, 256}.
__device__ __forceinline__ float2 block_reduce2(float s, float ss) {
    __shared__ float sh[64];
    int lane = threadIdx.x & 31, w = threadIdx.x >> 5;
#pragma unroll
    for (int o = 16; o; o >>= 1) {
        s  += __shfl_down_sync(0xffffffffu, s,  o);
        ss += __shfl_down_sync(0xffffffffu, ss, o);
    }
    if (lane == 0) { sh[w] = s; sh[32 + w] = ss; }
    __syncthreads();
    int nw = (blockDim.x + 31) >> 5;
    if (w == 0) {
        s  = (lane < nw) ? sh[lane]      : 0.0f;
        ss = (lane < nw) ? sh[32 + lane] : 0.0f;
#pragma unroll
        for (int o = 16; o; o >>= 1) {
            s  += __shfl_down_sync(0xffffffffu, s,  o);
            ss += __shfl_down_sync(0xffffffffu, ss, o);
        }
        if (lane == 0) { sh[0] = s; sh[32] = ss; }
    }
    __syncthreads();
    return make_float2(sh[0], sh[32]);
}

// ---------------- K0: fold LN affine into W1/b1 --------------------------------
// Wp[k,n] = g[k]*W[k,n];  b1p[n] = b1[n] + sum_k bln[k]*W[k,n]
__global__ void prep_kernel(const float* __restrict__ W, const float* __restrict__ g,
                            const float* __restrict__ bln, const float* __restrict__ b1,
                            float* __restrict__ Wp, float* __restrict__ b1p,
                            int Kd, int Nc) {
    int n = blockIdx.x * blockDim.x + threadIdx.x;
    if (n >= Nc) return;
    float acc = b1[n];
    for (int k = 0; k < Kd; k++) {
        float w = W[(size_t)k * Nc + n];
        Wp[(size_t)k * Nc + n] = g[k] * w;
        acc += bln[k] * w;
    }
    b1p[n] = acc;
}

// ---------------- K1: LN (normalize only, no affine) for image tokens ----------
__global__ void ln_img_kernel(const float* __restrict__ x, float* __restrict__ y) {
    int row = blockIdx.x, tid = threadIdx.x;   // 256 threads, 768 cols
    const float* xr = x + (size_t)row * IDim;
    float v0 = xr[tid], v1 = xr[tid + 256], v2 = xr[tid + 512];
    float s = v0 + v1 + v2;
    float ss = v0 * v0 + v1 * v1 + v2 * v2;
    float2 r = block_reduce2(s, ss);
    float mean = r.x * (1.0f / 768.0f);
    float var  = fmaxf(r.y * (1.0f / 768.0f) - mean * mean, 0.0f);
    float rstd = rsqrtf(var + 1e-5f);
    float* yr = y + (size_t)row * IDim;
    yr[tid]       = (v0 - mean) * rstd;
    yr[tid + 256] = (v1 - mean) * rstd;
    yr[tid + 512] = (v2 - mean) * rstd;
}

// ---------------- K2: generic 128x128x8 SGEMM with fused epilogue --------------
// ACT: 0 = none, 1 = exact gelu, 2 = final combine (pt + sigmoid(gate)*delta)*pv
template <int ACT>
__global__ __launch_bounds__(256)
void gemm_kernel(const float* __restrict__ A, const float* __restrict__ W,
                 const float* __restrict__ bias, float* __restrict__ C,
                 int R, int Kd, int Nc,
                 const float* __restrict__ gbuf, const float* __restrict__ ptb,
                 const int* __restrict__ pvm) {
    __shared__ float As[8][132];   // padded: conflict-free transpose store
    __shared__ float Bs[8][128];

    int tid = threadIdx.x;
    int tx = tid & 15, ty = tid >> 4;
    int row0 = blockIdx.y * 128, col0 = blockIdx.x * 128;

    int a_row = tid >> 1;
    int a_k   = (tid & 1) << 2;
    int b_k   = tid >> 5;
    int b_n   = (tid & 31) << 2;

    const float* Ap = A + (size_t)(row0 + a_row) * Kd + a_k;
    const float* Wq = W + (size_t)b_k * Nc + col0 + b_n;

    float acc[8][8];
#pragma unroll
    for (int i = 0; i < 8; i++)
#pragma unroll
        for (int j = 0; j < 8; j++) acc[i][j] = 0.0f;

    int nk = Kd >> 3;
    for (int t = 0; t < nk; t++) {
        float4 av = *(const float4*)Ap;
        float4 bv = *(const float4*)Wq;
        Ap += 8;
        Wq += (size_t)8 * Nc;
        As[a_k + 0][a_row] = av.x;
        As[a_k + 1][a_row] = av.y;
        As[a_k + 2][a_row] = av.z;
        As[a_k + 3][a_row] = av.w;
        *(float4*)&Bs[b_k][b_n] = bv;
        __syncthreads();
#pragma unroll
        for (int k = 0; k < 8; k++) {
            float4 a0 = *(const float4*)&As[k][ty * 4];
            float4 a1 = *(const float4*)&As[k][ty * 4 + 64];
            float4 b0 = *(const float4*)&Bs[k][tx * 4];
            float4 b1 = *(const float4*)&Bs[k][tx * 4 + 64];
            float am[8]  = {a0.x, a0.y, a0.z, a0.w, a1.x, a1.y, a1.z, a1.w};
            float bm2[8] = {b0.x, b0.y, b0.z, b0.w, b1.x, b1.y, b1.z, b1.w};
#pragma unroll
            for (int i = 0; i < 8; i++)
#pragma unroll
                for (int j = 0; j < 8; j++)
                    acc[i][j] = fmaf(am[i], bm2[j], acc[i][j]);
        }
        __syncthreads();
    }

#pragma unroll
    for (int ih = 0; ih < 2; ih++)
#pragma unroll
        for (int i2 = 0; i2 < 4; i2++) {
            int r = row0 + ih * 64 + ty * 4 + i2;
#pragma unroll
            for (int jh = 0; jh < 2; jh++) {
                int c = col0 + jh * 64 + tx * 4;
                float4 bv = *(const float4*)&bias[c];
                float4 v;
                v.x = acc[ih * 4 + i2][jh * 4 + 0] + bv.x;
                v.y = acc[ih * 4 + i2][jh * 4 + 1] + bv.y;
                v.z = acc[ih * 4 + i2][jh * 4 + 2] + bv.z;
                v.w = acc[ih * 4 + i2][jh * 4 + 3] + bv.w;
                if (ACT == 1) {
                    v.x = gelu_f(v.x); v.y = gelu_f(v.y);
                    v.z = gelu_f(v.z); v.w = gelu_f(v.w);
                }
                size_t off = (size_t)r * Nc + c;
                if (ACT == 2) {
                    float4 g4 = *(const float4*)(gbuf + off);
                    float4 p4 = *(const float4*)(ptb + off);
                    float pv = pvm[r] ? 1.0f : 0.0f;
                    v.x = (p4.x + sigmoid_f(g4.x) * v.x) * pv;
                    v.y = (p4.y + sigmoid_f(g4.y) * v.y) * pv;
                    v.z = (p4.z + sigmoid_f(g4.z) * v.z) * pv;
                    v.w = (p4.w + sigmoid_f(g4.w) * v.w) * pv;
                }
                *(float4*)&C[off] = v;
            }
        }
}

// ---------------- K3: kNN top-3 + inverse-distance weights ---------------------
__global__ __launch_bounds__(256)
void knn_kernel(const float* __restrict__ pc, const float* __restrict__ ic,
                const int* __restrict__ imask,
                int* __restrict__ knn_idx, float* __restrict__ knn_w) {
    __shared__ float4 cs[Mm];     // (x,y,z, ssq-or-inf)  16 KB
    int b = blockIdx.x;
    const float INFV = __int_as_float(0x7f800000);
    for (int m = threadIdx.x; m < Mm; m += 256) {
        size_t ci = ((size_t)b * Mm + m) * 3;
        float x = ic[ci], y = ic[ci + 1], z = ic[ci + 2];
        float s2 = imask[b * Mm + m] ? (x * x + y * y + z * z) : INFV;
        cs[m] = make_float4(x, y, z, s2);
    }
    __syncthreads();

    int n = blockIdx.y * 256 + threadIdx.x;
    size_t pidx = (size_t)b * Nn + n;
    float qx = pc[pidx * 3], qy = pc[pidx * 3 + 1], qz = pc[pidx * 3 + 2];
    float q2 = qx * qx + qy * qy + qz * qz;

    float d0 = INFV, d1 = INFV, d2v = INFV;
    int j0 = 0, j1 = 0, j2 = 0;
#pragma unroll 4
    for (int m = 0; m < Mm; m++) {
        float4 c = cs[m];
        float d = fmaxf(q2 + c.w - 2.0f * (qx * c.x + qy * c.y + qz * c.z), 0.0f);
        if (d < d2v) {
            if (d < d1) {
                d2v = d1; j2 = j1;
                if (d < d0) { d1 = d0; j1 = j0; d0 = d; j0 = m; }
                else        { d1 = d;  j1 = m; }
            } else { d2v = d; j2 = m; }
        }
    }
    // weights: 1/clip(sqrt(d),1e-6); invalid (inf) -> 0 automatically
    float w0 = 1.0f / fmaxf(sqrtf(d0),  1e-6f);
    float w1 = 1.0f / fmaxf(sqrtf(d1),  1e-6f);
    float w2 = 1.0f / fmaxf(sqrtf(d2v), 1e-6f);
    float inv = 1.0f / fmaxf(w0 + w1 + w2, 1e-6f);
    size_t base = pidx * 3;
    knn_idx[base + 0] = b * Mm + j0;
    knn_idx[base + 1] = b * Mm + j1;
    knn_idx[base + 2] = b * Mm + j2;
    knn_w[base + 0] = w0 * inv;
    knn_w[base + 1] = w1 * inv;
    knn_w[base + 2] = w2 * inv;
}

// ---------------- K4: gather aligned + concat + LN(normalize-only) -------------
__global__ __launch_bounds__(128)
void fin_ln_kernel(const float* __restrict__ pt, const int* __restrict__ pvm,
                   float* __restrict__ out) {
    int p = blockIdx.x, tid = threadIdx.x;   // 128 threads * float4 = 512 cols
    float4 v;
    if (tid < 64) {
        v = *(const float4*)&pt[(size_t)p * ODim + tid * 4];
    } else {
        int base = p * 3;
        int i0 = g_knn_idx[base], i1 = g_knn_idx[base + 1], i2 = g_knn_idx[base + 2];
        float w0 = g_knn_w[base], w1 = g_knn_w[base + 1], w2 = g_knn_w[base + 2];
        int o = (tid - 64) * 4;
        float4 f0 = *(const float4*)&g_imgfeat[(size_t)i0 * ODim + o];
        float4 f1 = *(const float4*)&g_imgfeat[(size_t)i1 * ODim + o];
        float4 f2 = *(const float4*)&g_imgfeat[(size_t)i2 * ODim + o];
        float pv = pvm[p] ? 1.0f : 0.0f;
        v.x = (w0 * f0.x + w1 * f1.x + w2 * f2.x) * pv;
        v.y = (w0 * f0.y + w1 * f1.y + w2 * f2.y) * pv;
        v.z = (w0 * f0.z + w1 * f1.z + w2 * f2.z) * pv;
        v.w = (w0 * f0.w + w1 * f1.w + w2 * f2.w) * pv;
    }
    float s  = v.x + v.y + v.z + v.w;
    float ss = v.x * v.x + v.y * v.y + v.z * v.z + v.w * v.w;
    float2 r = block_reduce2(s, ss);
    float mean = r.x * (1.0f / 512.0f);
    float var  = fmaxf(r.y * (1.0f / 512.0f) - mean * mean, 0.0f);
    float rstd = rsqrtf(var + 1e-5f);
    float4 o4;
    o4.x = (v.x - mean) * rstd;
    o4.y = (v.y - mean) * rstd;
    o4.z = (v.z - mean) * rstd;
    o4.w = (v.w - mean) * rstd;
    *(float4*)&out[(size_t)p * 512 + tid * 4] = o4;
}

// ---------------- launch -------------------------------------------------------
extern "C" void kernel_launch(void* const* d_in, const int* in_sizes, int n_in,
                              void* d_out, int out_size) {
    const float* pt      = (const float*)d_in[0];   // [B,N,256]
    const float* pc      = (const float*)d_in[1];   // [B,N,3]
    const float* it      = (const float*)d_in[2];   // [B,M,768]
    const float* icd     = (const float*)d_in[3];   // [B,M,3]
    const int*   pvm     = (const int*)d_in[4];     // [B,N] bool->i32
    const int*   ivm     = (const int*)d_in[5];     // [B,M] bool->i32
    const float* ip_ln_g = (const float*)d_in[6];
    const float* ip_ln_b = (const float*)d_in[7];
    const float* ip_w1   = (const float*)d_in[8];
    const float* ip_b1   = (const float*)d_in[9];
    const float* ip_w2   = (const float*)d_in[10];
    const float* ip_b2   = (const float*)d_in[11];
    const float* g_ln_g  = (const float*)d_in[12];
    const float* g_ln_b  = (const float*)d_in[13];
    const float* g_w1    = (const float*)d_in[14];
    const float* g_b1    = (const float*)d_in[15];
    const float* g_w2    = (const float*)d_in[16];
    const float* g_b2    = (const float*)d_in[17];
    const float* d_ln_g  = (const float*)d_in[18];
    const float* d_ln_b  = (const float*)d_in[19];
    const float* d_w1    = (const float*)d_in[20];
    const float* d_b1    = (const float*)d_in[21];
    const float* d_w2    = (const float*)d_in[22];
    const float* d_b2    = (const float*)d_in[23];
    float* out = (float*)d_out;

    float *xln, *hbuf, *imgf, *finln, *gate, *knnw;
    float *wpip, *wpg, *wpd, *bpip, *bpg, *bpd;
    int* knni;
    cudaGetSymbolAddress((void**)&xln,   g_xln);
    cudaGetSymbolAddress((void**)&hbuf,  g_hbuf);
    cudaGetSymbolAddress((void**)&imgf,  g_imgfeat);
    cudaGetSymbolAddress((void**)&finln, g_finln);
    cudaGetSymbolAddress((void**)&gate,  g_gate);
    cudaGetSymbolAddress((void**)&knni,  g_knn_idx);
    cudaGetSymbolAddress((void**)&knnw,  g_knn_w);
    cudaGetSymbolAddress((void**)&wpip,  g_wp_ip);
    cudaGetSymbolAddress((void**)&wpg,   g_wp_g);
    cudaGetSymbolAddress((void**)&wpd,   g_wp_d);
    cudaGetSymbolAddress((void**)&bpip,  g_bp_ip);
    cudaGetSymbolAddress((void**)&bpg,   g_bp_g);
    cudaGetSymbolAddress((void**)&bpd,   g_bp_d);

    // 0) fold LN affine into first-layer weights
    prep_kernel<<<2, 256>>>(ip_w1, ip_ln_g, ip_ln_b, ip_b1, wpip, bpip, IDim, HDim);
    prep_kernel<<<2, 256>>>(g_w1,  g_ln_g,  g_ln_b,  g_b1,  wpg,  bpg,  2 * ODim, HDim);
    prep_kernel<<<2, 256>>>(d_w1,  d_ln_g,  d_ln_b,  d_b1,  wpd,  bpd,  2 * ODim, HDim);

    // 1) image MLP: LN -> gelu(x@w1'+b1') -> @w2+b2
    ln_img_kernel<<<ROWS_IMG, 256>>>(it, xln);
    gemm_kernel<1><<<dim3(HDim / 128, ROWS_IMG / 128), 256>>>(
        xln, wpip, bpip, hbuf, ROWS_IMG, IDim, HDim, nullptr, nullptr, nullptr);
    gemm_kernel<0><<<dim3(ODim / 128, ROWS_IMG / 128), 256>>>(
        hbuf, ip_w2, ip_b2, imgf, ROWS_IMG, HDim, ODim, nullptr, nullptr, nullptr);

    // 2) kNN top-3 over image coords
    knn_kernel<<<dim3(Bb, Nn / 256), 256>>>(pc, icd, ivm, knni, knnw);

    // 3) gather+concat+LN(normalize only) -> fin̂ (shared by gate & delta)
    fin_ln_kernel<<<ROWS_PT, 128>>>(pt, pvm, finln);

    // 4) gate MLP
    gemm_kernel<1><<<dim3(HDim / 128, ROWS_PT / 128), 256>>>(
        finln, wpg, bpg, hbuf, ROWS_PT, 2 * ODim, HDim, nullptr, nullptr, nullptr);
    gemm_kernel<0><<<dim3(ODim / 128, ROWS_PT / 128), 256>>>(
        hbuf, g_w2, g_b2, gate, ROWS_PT, HDim, ODim, nullptr, nullptr, nullptr);

    // 5) delta MLP + fused final combine: out = (pt + sigmoid(gate)*delta)*pv
    gemm_kernel<1><<<dim3(HDim / 128, ROWS_PT / 128), 256>>>(
        finln, wpd, bpd, hbuf, ROWS_PT, 2 * ODim, HDim, nullptr, nullptr, nullptr);
    gemm_kernel<2><<<dim3(ODim / 128, ROWS_PT / 128), 256>>>(
        hbuf, d_w2, d_b2, out, ROWS_PT, HDim, ODim, gate, pt, pvm);
}

// round 3
// speedup vs baseline: 2.0277x; 2.0277x over previous
#include <cuda_runtime.h>
#include <math.h>
#include <stdint.h>

// Problem dims (fixed by the dataset)
#define Bb   16
#define Nn   4096
#define Mm   1024
#define IDim 768
#define HDim 512
#define ODim 256
#define ROWS_IMG (Bb*Mm)   // 16384
#define ROWS_PT  (Bb*Nn)   // 65536

// ---------------- scratch (device globals; no allocation allowed) -------------
__device__ float g_xln[ROWS_IMG * IDim];            // LN-normalized image tokens (tf32-rounded)
__device__ float g_hbuf[ROWS_PT * HDim];            // hidden buffer (tf32-rounded)
__device__ float g_imgfeat[ROWS_IMG * ODim];        // image MLP output
__device__ float g_finln[ROWS_PT * (2 * ODim)];     // normalized fin (tf32-rounded)
__device__ float g_gate[ROWS_PT * ODim];            // gate pre-sigmoid
__device__ int   g_knn_idx[ROWS_PT * 3];
__device__ float g_knn_w[ROWS_PT * 3];
// transposed (and LN-folded for layer-1) weights: [N,K] K-major, tf32-rounded
__device__ float g_wt_ip1[HDim * IDim];
__device__ float g_wt_g1[HDim * (2*ODim)];
__device__ float g_wt_d1[HDim * (2*ODim)];
__device__ float g_wt_ip2[ODim * HDim];
__device__ float g_wt_g2[ODim * HDim];
__device__ float g_wt_d2[ODim * HDim];
__device__ float g_bp_ip[HDim];
__device__ float g_bp_g[HDim];
__device__ float g_bp_d[HDim];

// ---------------- helpers ------------------------------------------------------
__device__ __forceinline__ float tf32_rne(float v) {
    uint32_t u;
    asm("cvt.rna.tf32.f32 %0, %1;" : "=r"(u) : "f"(v));
    return __uint_as_float(u);
}
__device__ __forceinline__ float gelu_f(float x) {
    return 0.5f * x * (1.0f + erff(x * 0.70710678118654752f));
}
__device__ __forceinline__ float sigmoid_f(float x) {
    return 1.0f / (1.0f + __expf(-x));
}
__device__ __forceinline__ float2 block_reduce2(float s, float ss) {
    __shared__ float sh[64];
    int lane = threadIdx.x & 31, w = threadIdx.x >> 5;
#pragma unroll
    for (int o = 16; o; o >>= 1) {
        s  += __shfl_down_sync(0xffffffffu, s,  o);
        ss += __shfl_down_sync(0xffffffffu, ss, o);
    }
    if (lane == 0) { sh[w] = s; sh[32 + w] = ss; }
    __syncthreads();
    int nw = (blockDim.x + 31) >> 5;
    if (w == 0) {
        s  = (lane < nw) ? sh[lane]      : 0.0f;
        ss = (lane < nw) ? sh[32 + lane] : 0.0f;
#pragma unroll
        for (int o = 16; o; o >>= 1) {
            s  += __shfl_down_sync(0xffffffffu, s,  o);
            ss += __shfl_down_sync(0xffffffffu, ss, o);
        }
        if (lane == 0) { sh[0] = s; sh[32] = ss; }
    }
    __syncthreads();
    return make_float2(sh[0], sh[32]);
}

// ---------------- K0a: fold LN affine + transpose W1 (tf32-rounded) -------------
__global__ void prep_fold_T(const float* __restrict__ W, const float* __restrict__ g,
                            const float* __restrict__ bln, const float* __restrict__ b1,
                            float* __restrict__ Wt, float* __restrict__ b1p,
                            int Kd, int Nc) {
    int n = blockIdx.x * blockDim.x + threadIdx.x;
    if (n >= Nc) return;
    float acc = b1[n];
    for (int k = 0; k < Kd; k++) {
        float w = W[(size_t)k * Nc + n];
        Wt[(size_t)n * Kd + k] = tf32_rne(g[k] * w);
        acc += bln[k] * w;
    }
    b1p[n] = acc;
}
// ---------------- K0b: transpose (tf32-rounded) ---------------------------------
__global__ void transpose_k(const float* __restrict__ W, float* __restrict__ Wt,
                            int Kd, int Nc) {
    int idx = blockIdx.x * blockDim.x + threadIdx.x;
    if (idx >= Kd * Nc) return;
    int k = idx / Nc, n = idx % Nc;
    Wt[(size_t)n * Kd + k] = tf32_rne(W[idx]);
}

// ---------------- K1: LN (normalize only) for image tokens, tf32-rounded --------
__global__ void ln_img_kernel(const float* __restrict__ x, float* __restrict__ y) {
    int row = blockIdx.x, tid = threadIdx.x;
    const float* xr = x + (size_t)row * IDim;
    float v0 = xr[tid], v1 = xr[tid + 256], v2 = xr[tid + 512];
    float s = v0 + v1 + v2;
    float ss = v0 * v0 + v1 * v1 + v2 * v2;
    float2 r = block_reduce2(s, ss);
    float mean = r.x * (1.0f / 768.0f);
    float var  = fmaxf(r.y * (1.0f / 768.0f) - mean * mean, 0.0f);
    float rstd = rsqrtf(var + 1e-5f);
    float* yr = y + (size_t)row * IDim;
    yr[tid]       = tf32_rne((v0 - mean) * rstd);
    yr[tid + 256] = tf32_rne((v1 - mean) * rstd);
    yr[tid + 512] = tf32_rne((v2 - mean) * rstd);
}

// ---------------- K2: tf32 mma.sync GEMM ----------------------------------------
// C[R,Nc] = A[R,Kd] @ Bt[Nc,Kd]^T, 128x128 tile, K-tile 32, 3-stage cp.async.
// ACT: 0 none, 1 gelu (tf32-round output), 2 final combine (pt+sigmoid(gate)*delta)*pv
#define KTILE   32
#define STAGES  3
#define PITCH   36                         // floats per smem row (32 data + 4 pad)
#define TILE_B  (128 * PITCH * 4)          // 18432 bytes per tile
#define STAGE_B (2 * TILE_B)               // A + B per stage
#define SM_TOTAL (STAGES * STAGE_B)        // 110592 bytes

#define CPA_COMMIT() asm volatile("cp.async.commit_group;" ::: "memory")
#define CPA_WAIT2()  asm volatile("cp.async.wait_group 2;" ::: "memory")

__device__ __forceinline__ uint32_t smem_u32(const void* p) {
    uint32_t a;
    asm("{ .reg .u64 t; cvta.to.shared.u64 t, %1; cvt.u32.u64 %0, t; }" : "=r"(a) : "l"(p));
    return a;
}

__device__ __forceinline__ void load_tile(uint32_t sbase, const float* gbase, int ld) {
    int t = threadIdx.x;
#pragma unroll
    for (int i = 0; i < 4; i++) {
        int idx = t + i * 256;            // 0..1023 chunks of 16B
        int r = idx >> 3, c = idx & 7;
        uint32_t so = sbase + (uint32_t)(r * (PITCH * 4) + c * 16);
        const float* gp = gbase + (size_t)r * ld + c * 4;
        asm volatile("cp.async.cg.shared.global [%0], [%1], 16;" :: "r"(so), "l"(gp));
    }
}

__device__ __forceinline__ void mma_tf32(float* d, const uint32_t* a, const uint32_t* b) {
    asm volatile(
        "mma.sync.aligned.m16n8k8.row.col.f32.tf32.tf32.f32 "
        "{%0,%1,%2,%3}, {%4,%5,%6,%7}, {%8,%9}, {%0,%1,%2,%3};"
        : "+f"(d[0]), "+f"(d[1]), "+f"(d[2]), "+f"(d[3])
        : "r"(a[0]), "r"(a[1]), "r"(a[2]), "r"(a[3]), "r"(b[0]), "r"(b[1]));
}

template <int ACT>
__global__ __launch_bounds__(256)
void mma_gemm(const float* __restrict__ A, const float* __restrict__ Bt,
              const float* __restrict__ bias, float* __restrict__ C,
              int Kd, int Nc,
              const float* __restrict__ gbuf, const float* __restrict__ ptb,
              const int* __restrict__ pvm) {
    extern __shared__ char smem[];
    uint32_t sb = smem_u32(smem);
    int tid = threadIdx.x, wid = tid >> 5, lane = tid & 31;
    int wm = wid & 1, wn = wid >> 1;              // 2x4 warp grid
    int g = lane >> 2, i4 = lane & 3;
    int row0 = blockIdx.y * 128, col0 = blockIdx.x * 128;

    const int NK = Kd / KTILE;
    const float* Ag = A  + (size_t)row0 * Kd;
    const float* Bg = Bt + (size_t)col0 * Kd;

    // prologue
#pragma unroll
    for (int p = 0; p < STAGES; p++) {
        load_tile(sb + p * STAGE_B,          Ag + p * KTILE, Kd);
        load_tile(sb + p * STAGE_B + TILE_B, Bg + p * KTILE, Kd);
        CPA_COMMIT();
    }

    float acc[4][4][4];
#pragma unroll
    for (int mf = 0; mf < 4; mf++)
#pragma unroll
        for (int nf = 0; nf < 4; nf++)
#pragma unroll
            for (int e = 0; e < 4; e++) acc[mf][nf][e] = 0.0f;

    for (int kt = 0; kt < NK; kt++) {
        int s = kt % STAGES;
        CPA_WAIT2();
        __syncthreads();
        const float* As = (const float*)(smem + s * STAGE_B);
        const float* Bs = (const float*)(smem + s * STAGE_B + TILE_B);
#pragma unroll
        for (int ks = 0; ks < 4; ks++) {
            int k0 = ks * 8 + i4;
            uint32_t a[4][4], b[4][2];
#pragma unroll
            for (int mf = 0; mf < 4; mf++) {
                int r = wm * 64 + mf * 16 + g;
                a[mf][0] = __float_as_uint(As[r * PITCH + k0]);
                a[mf][1] = __float_as_uint(As[(r + 8) * PITCH + k0]);
                a[mf][2] = __float_as_uint(As[r * PITCH + k0 + 4]);
                a[mf][3] = __float_as_uint(As[(r + 8) * PITCH + k0 + 4]);
            }
#pragma unroll
            for (int nf = 0; nf < 4; nf++) {
                int c = wn * 32 + nf * 8 + g;
                b[nf][0] = __float_as_uint(Bs[c * PITCH + k0]);
                b[nf][1] = __float_as_uint(Bs[c * PITCH + k0 + 4]);
            }
#pragma unroll
            for (int mf = 0; mf < 4; mf++)
#pragma unroll
                for (int nf = 0; nf < 4; nf++)
                    mma_tf32(acc[mf][nf], a[mf], b[nf]);
        }
        __syncthreads();
        if (kt + STAGES < NK) {
            load_tile(sb + s * STAGE_B,          Ag + (size_t)(kt + STAGES) * KTILE, Kd);
            load_tile(sb + s * STAGE_B + TILE_B, Bg + (size_t)(kt + STAGES) * KTILE, Kd);
        }
        CPA_COMMIT();
    }

    // epilogue: store straight from fragments (float2 per thread = 32B sectors)
#pragma unroll
    for (int mf = 0; mf < 4; mf++) {
        int r_lo = row0 + wm * 64 + mf * 16 + g;
#pragma unroll
        for (int nf = 0; nf < 4; nf++) {
            int col = col0 + wn * 32 + nf * 8 + i4 * 2;
            float b0 = bias[col], b1 = bias[col + 1];
#pragma unroll
            for (int h = 0; h < 2; h++) {
                int row = r_lo + h * 8;
                float v0 = acc[mf][nf][h * 2 + 0] + b0;
                float v1 = acc[mf][nf][h * 2 + 1] + b1;
                if (ACT == 1) {
                    v0 = tf32_rne(gelu_f(v0));
                    v1 = tf32_rne(gelu_f(v1));
                }
                size_t off = (size_t)row * Nc + col;
                if (ACT == 2) {
                    float2 g4 = *(const float2*)(gbuf + off);
                    float2 p4 = *(const float2*)(ptb + off);
                    float m = pvm[row] ? 1.0f : 0.0f;
                    v0 = (p4.x + sigmoid_f(g4.x) * v0) * m;
                    v1 = (p4.y + sigmoid_f(g4.y) * v1) * m;
                }
                float2 o2 = make_float2(v0, v1);
                *(float2*)(C + off) = o2;
            }
        }
    }
}

// ---------------- K3: kNN top-3 + inverse-distance weights ----------------------
__global__ __launch_bounds__(256)
void knn_kernel(const float* __restrict__ pc, const float* __restrict__ ic,
                const int* __restrict__ imask,
                int* __restrict__ knn_idx, float* __restrict__ knn_w) {
    __shared__ float4 cs[Mm];
    int b = blockIdx.x;
    const float INFV = __int_as_float(0x7f800000);
    for (int m = threadIdx.x; m < Mm; m += 256) {
        size_t ci = ((size_t)b * Mm + m) * 3;
        float x = ic[ci], y = ic[ci + 1], z = ic[ci + 2];
        float s2 = imask[b * Mm + m] ? (x * x + y * y + z * z) : INFV;
        cs[m] = make_float4(x, y, z, s2);
    }
    __syncthreads();

    int n = blockIdx.y * 256 + threadIdx.x;
    size_t pidx = (size_t)b * Nn + n;
    float qx = pc[pidx * 3], qy = pc[pidx * 3 + 1], qz = pc[pidx * 3 + 2];
    float q2 = qx * qx + qy * qy + qz * qz;

    float d0 = INFV, d1 = INFV, d2v = INFV;
    int j0 = 0, j1 = 0, j2 = 0;
#pragma unroll 4
    for (int m = 0; m < Mm; m++) {
        float4 c = cs[m];
        float d = fmaxf(q2 + c.w - 2.0f * (qx * c.x + qy * c.y + qz * c.z), 0.0f);
        if (d < d2v) {
            if (d < d1) {
                d2v = d1; j2 = j1;
                if (d < d0) { d1 = d0; j1 = j0; d0 = d; j0 = m; }
                else        { d1 = d;  j1 = m; }
            } else { d2v = d; j2 = m; }
        }
    }
    float w0 = 1.0f / fmaxf(sqrtf(d0),  1e-6f);
    float w1 = 1.0f / fmaxf(sqrtf(d1),  1e-6f);
    float w2 = 1.0f / fmaxf(sqrtf(d2v), 1e-6f);
    float inv = 1.0f / fmaxf(w0 + w1 + w2, 1e-6f);
    size_t base = pidx * 3;
    knn_idx[base + 0] = b * Mm + j0;
    knn_idx[base + 1] = b * Mm + j1;
    knn_idx[base + 2] = b * Mm + j2;
    knn_w[base + 0] = w0 * inv;
    knn_w[base + 1] = w1 * inv;
    knn_w[base + 2] = w2 * inv;
}

// ---------------- K4: gather aligned + concat + LN, tf32-rounded ----------------
__global__ __launch_bounds__(128)
void fin_ln_kernel(const float* __restrict__ pt, const int* __restrict__ pvm,
                   float* __restrict__ out) {
    int p = blockIdx.x, tid = threadIdx.x;
    float4 v;
    if (tid < 64) {
        v = *(const float4*)&pt[(size_t)p * ODim + tid * 4];
    } else {
        int base = p * 3;
        int i0 = g_knn_idx[base], i1 = g_knn_idx[base + 1], i2 = g_knn_idx[base + 2];
        float w0 = g_knn_w[base], w1 = g_knn_w[base + 1], w2 = g_knn_w[base + 2];
        int o = (tid - 64) * 4;
        float4 f0 = *(const float4*)&g_imgfeat[(size_t)i0 * ODim + o];
        float4 f1 = *(const float4*)&g_imgfeat[(size_t)i1 * ODim + o];
        float4 f2 = *(const float4*)&g_imgfeat[(size_t)i2 * ODim + o];
        float pv = pvm[p] ? 1.0f : 0.0f;
        v.x = (w0 * f0.x + w1 * f1.x + w2 * f2.x) * pv;
        v.y = (w0 * f0.y + w1 * f1.y + w2 * f2.y) * pv;
        v.z = (w0 * f0.z + w1 * f1.z + w2 * f2.z) * pv;
        v.w = (w0 * f0.w + w1 * f1.w + w2 * f2.w) * pv;
    }
    float s  = v.x + v.y + v.z + v.w;
    float ss = v.x * v.x + v.y * v.y + v.z * v.z + v.w * v.w;
    float2 r = block_reduce2(s, ss);
    float mean = r.x * (1.0f / 512.0f);
    float var  = fmaxf(r.y * (1.0f / 512.0f) - mean * mean, 0.0f);
    float rstd = rsqrtf(var + 1e-5f);
    float4 o4;
    o4.x = tf32_rne((v.x - mean) * rstd);
    o4.y = tf32_rne((v.y - mean) * rstd);
    o4.z = tf32_rne((v.z - mean) * rstd);
    o4.w = tf32_rne((v.w - mean) * rstd);
    *(float4*)&out[(size_t)p * 512 + tid * 4] = o4;
}

// ---------------- launch ---------------------------------------------------------
extern "C" void kernel_launch(void* const* d_in, const int* in_sizes, int n_in,
                              void* d_out, int out_size) {
    const float* pt      = (const float*)d_in[0];
    const float* pc      = (const float*)d_in[1];
    const float* it      = (const float*)d_in[2];
    const float* icd     = (const float*)d_in[3];
    const int*   pvm     = (const int*)d_in[4];
    const int*   ivm     = (const int*)d_in[5];
    const float* ip_ln_g = (const float*)d_in[6];
    const float* ip_ln_b = (const float*)d_in[7];
    const float* ip_w1   = (const float*)d_in[8];
    const float* ip_b1   = (const float*)d_in[9];
    const float* ip_w2   = (const float*)d_in[10];
    const float* ip_b2   = (const float*)d_in[11];
    const float* g_ln_g  = (const float*)d_in[12];
    const float* g_ln_b  = (const float*)d_in[13];
    const float* g_w1    = (const float*)d_in[14];
    const float* g_b1    = (const float*)d_in[15];
    const float* g_w2    = (const float*)d_in[16];
    const float* g_b2    = (const float*)d_in[17];
    const float* d_ln_g  = (const float*)d_in[18];
    const float* d_ln_b  = (const float*)d_in[19];
    const float* d_w1    = (const float*)d_in[20];
    const float* d_b1    = (const float*)d_in[21];
    const float* d_w2    = (const float*)d_in[22];
    const float* d_b2    = (const float*)d_in[23];
    float* out = (float*)d_out;

    float *xln, *hbuf, *imgf, *finln, *gate, *knnw;
    float *wt_ip1, *wt_g1, *wt_d1, *wt_ip2, *wt_g2, *wt_d2, *bpip, *bpg, *bpd;
    int* knni;
    cudaGetSymbolAddress((void**)&xln,    g_xln);
    cudaGetSymbolAddress((void**)&hbuf,   g_hbuf);
    cudaGetSymbolAddress((void**)&imgf,   g_imgfeat);
    cudaGetSymbolAddress((void**)&finln,  g_finln);
    cudaGetSymbolAddress((void**)&gate,   g_gate);
    cudaGetSymbolAddress((void**)&knni,   g_knn_idx);
    cudaGetSymbolAddress((void**)&knnw,   g_knn_w);
    cudaGetSymbolAddress((void**)&wt_ip1, g_wt_ip1);
    cudaGetSymbolAddress((void**)&wt_g1,  g_wt_g1);
    cudaGetSymbolAddress((void**)&wt_d1,  g_wt_d1);
    cudaGetSymbolAddress((void**)&wt_ip2, g_wt_ip2);
    cudaGetSymbolAddress((void**)&wt_g2,  g_wt_g2);
    cudaGetSymbolAddress((void**)&wt_d2,  g_wt_d2);
    cudaGetSymbolAddress((void**)&bpip,   g_bp_ip);
    cudaGetSymbolAddress((void**)&bpg,    g_bp_g);
    cudaGetSymbolAddress((void**)&bpd,    g_bp_d);

    cudaFuncSetAttribute(mma_gemm<0>, cudaFuncAttributeMaxDynamicSharedMemorySize, SM_TOTAL);
    cudaFuncSetAttribute(mma_gemm<1>, cudaFuncAttributeMaxDynamicSharedMemorySize, SM_TOTAL);
    cudaFuncSetAttribute(mma_gemm<2>, cudaFuncAttributeMaxDynamicSharedMemorySize, SM_TOTAL);

    // 0) fold LN affine into W1 (+transpose); transpose W2s (all tf32-rounded)
    prep_fold_T<<<2, 256>>>(ip_w1, ip_ln_g, ip_ln_b, ip_b1, wt_ip1, bpip, IDim, HDim);
    prep_fold_T<<<2, 256>>>(g_w1,  g_ln_g,  g_ln_b,  g_b1,  wt_g1,  bpg,  2 * ODim, HDim);
    prep_fold_T<<<2, 256>>>(d_w1,  d_ln_g,  d_ln_b,  d_b1,  wt_d1,  bpd,  2 * ODim, HDim);
    transpose_k<<<(HDim * ODim + 255) / 256, 256>>>(ip_w2, wt_ip2, HDim, ODim);
    transpose_k<<<(HDim * ODim + 255) / 256, 256>>>(g_w2,  wt_g2,  HDim, ODim);
    transpose_k<<<(HDim * ODim + 255) / 256, 256>>>(d_w2,  wt_d2,  HDim, ODim);

    // 1) image MLP
    ln_img_kernel<<<ROWS_IMG, 256>>>(it, xln);
    mma_gemm<1><<<dim3(HDim / 128, ROWS_IMG / 128), 256, SM_TOTAL>>>(
        xln, wt_ip1, bpip, hbuf, IDim, HDim, nullptr, nullptr, nullptr);
    mma_gemm<0><<<dim3(ODim / 128, ROWS_IMG / 128), 256, SM_TOTAL>>>(
        hbuf, wt_ip2, ip_b2, imgf, HDim, ODim, nullptr, nullptr, nullptr);

    // 2) kNN top-3
    knn_kernel<<<dim3(Bb, Nn / 256), 256>>>(pc, icd, ivm, knni, knnw);

    // 3) gather+concat+LN -> fin̂
    fin_ln_kernel<<<ROWS_PT, 128>>>(pt, pvm, finln);

    // 4) gate MLP
    mma_gemm<1><<<dim3(HDim / 128, ROWS_PT / 128), 256, SM_TOTAL>>>(
        finln, wt_g1, bpg, hbuf, 2 * ODim, HDim, nullptr, nullptr, nullptr);
    mma_gemm<0><<<dim3(ODim / 128, ROWS_PT / 128), 256, SM_TOTAL>>>(
        hbuf, wt_g2, g_b2, gate, HDim, ODim, nullptr, nullptr, nullptr);

    // 5) delta MLP + fused final combine
    mma_gemm<1><<<dim3(HDim / 128, ROWS_PT / 128), 256, SM_TOTAL>>>(
        finln, wt_d1, bpd, hbuf, 2 * ODim, HDim, nullptr, nullptr, nullptr);
    mma_gemm<2><<<dim3(ODim / 128, ROWS_PT / 128), 256, SM_TOTAL>>>(
        hbuf, wt_d2, d_b2, out, HDim, ODim, gate, pt, pvm);
}

// round 4
// speedup vs baseline: 2.1796x; 1.0749x over previous
#include <cuda_runtime.h>
#include <math.h>
#include <stdint.h>

// Problem dims (fixed by the dataset)
#define Bb   16
#define Nn   4096
#define Mm   1024
#define IDim 768
#define HDim 512
#define ODim 256
#define ROWS_IMG (Bb*Mm)   // 16384
#define ROWS_PT  (Bb*Nn)   // 65536

// ---------------- scratch (device globals; no allocation allowed) -------------
__device__ float g_xln[ROWS_IMG * IDim];            // LN image tokens (tf32, k-permuted)
__device__ float g_hbuf[ROWS_PT * HDim];            // hidden buffer (tf32, k-permuted)
__device__ float g_imgfeat[ROWS_IMG * ODim];        // image MLP output (plain)
__device__ float g_finln[ROWS_PT * (2 * ODim)];     // normalized fin (tf32, k-permuted)
__device__ float g_gate[ROWS_PT * ODim];            // gate pre-sigmoid (plain)
__device__ int   g_knn_idx[ROWS_PT * 3];
__device__ float g_knn_w[ROWS_PT * 3];
// transposed (LN-folded for layer-1) weights: [N,K] K-major, tf32, k-permuted
__device__ float g_wt_ip1[HDim * IDim];
__device__ float g_wt_g1[HDim * (2*ODim)];
__device__ float g_wt_d1[HDim * (2*ODim)];
__device__ float g_wt_ip2[ODim * HDim];
__device__ float g_wt_g2[ODim * HDim];
__device__ float g_wt_d2[ODim * HDim];
__device__ float g_bp_ip[HDim];
__device__ float g_bp_g[HDim];
__device__ float g_bp_d[HDim];

// ---------------- helpers ------------------------------------------------------
// k-group permutation: within each 8-wide k group, value for original k goes to
// position q(k) = 2*(k&3) | ((k>>2)&1).  Fragment pair (k, k+4) becomes adjacent.
__device__ __forceinline__ int qmap(int k) {
    return (k & ~7) | ((k & 3) << 1) | ((k >> 2) & 1);
}
__device__ __forceinline__ float tf32_rne(float v) {
    uint32_t u;
    asm("cvt.rna.tf32.f32 %0, %1;" : "=r"(u) : "f"(v));
    return __uint_as_float(u);
}
__device__ __forceinline__ float gelu_f(float x) {
    return 0.5f * x * (1.0f + erff(x * 0.70710678118654752f));
}
__device__ __forceinline__ float sigmoid_f(float x) {
    return 1.0f / (1.0f + __expf(-x));
}
__device__ __forceinline__ float2 block_reduce2(float s, float ss) {
    __shared__ float sh[64];
    int lane = threadIdx.x & 31, w = threadIdx.x >> 5;
#pragma unroll
    for (int o = 16; o; o >>= 1) {
        s  += __shfl_down_sync(0xffffffffu, s,  o);
        ss += __shfl_down_sync(0xffffffffu, ss, o);
    }
    if (lane == 0) { sh[w] = s; sh[32 + w] = ss; }
    __syncthreads();
    int nw = (blockDim.x + 31) >> 5;
    if (w == 0) {
        s  = (lane < nw) ? sh[lane]      : 0.0f;
        ss = (lane < nw) ? sh[32 + lane] : 0.0f;
#pragma unroll
        for (int o = 16; o; o >>= 1) {
            s  += __shfl_down_sync(0xffffffffu, s,  o);
            ss += __shfl_down_sync(0xffffffffu, ss, o);
        }
        if (lane == 0) { sh[0] = s; sh[32] = ss; }
    }
    __syncthreads();
    return make_float2(sh[0], sh[32]);
}

// ---------------- K0a: fold LN affine + transpose W1 (tf32, permuted) -----------
__global__ void prep_fold_T(const float* __restrict__ W, const float* __restrict__ g,
                            const float* __restrict__ bln, const float* __restrict__ b1,
                            float* __restrict__ Wt, float* __restrict__ b1p,
                            int Kd, int Nc) {
    int n = blockIdx.x * blockDim.x + threadIdx.x;
    if (n >= Nc) return;
    float acc = b1[n];
    for (int k = 0; k < Kd; k++) {
        float w = W[(size_t)k * Nc + n];
        Wt[(size_t)n * Kd + qmap(k)] = tf32_rne(g[k] * w);
        acc += bln[k] * w;
    }
    b1p[n] = acc;
}
// ---------------- K0b: transpose (tf32, permuted) -------------------------------
__global__ void transpose_k(const float* __restrict__ W, float* __restrict__ Wt,
                            int Kd, int Nc) {
    int idx = blockIdx.x * blockDim.x + threadIdx.x;
    if (idx >= Kd * Nc) return;
    int k = idx / Nc, n = idx % Nc;
    Wt[(size_t)n * Kd + qmap(k)] = tf32_rne(W[idx]);
}

// ---------------- K1: LN (normalize only), tf32, permuted store -----------------
__global__ void ln_img_kernel(const float* __restrict__ x, float* __restrict__ y) {
    int row = blockIdx.x, tid = threadIdx.x;
    const float* xr = x + (size_t)row * IDim;
    float v0 = xr[tid], v1 = xr[tid + 256], v2 = xr[tid + 512];
    float s = v0 + v1 + v2;
    float ss = v0 * v0 + v1 * v1 + v2 * v2;
    float2 r = block_reduce2(s, ss);
    float mean = r.x * (1.0f / 768.0f);
    float var  = fmaxf(r.y * (1.0f / 768.0f) - mean * mean, 0.0f);
    float rstd = rsqrtf(var + 1e-5f);
    float* yr = y + (size_t)row * IDim;
    yr[qmap(tid)]       = tf32_rne((v0 - mean) * rstd);
    yr[qmap(tid + 256)] = tf32_rne((v1 - mean) * rstd);
    yr[qmap(tid + 512)] = tf32_rne((v2 - mean) * rstd);
}

// ---------------- K2: tf32 mma.sync GEMM, 2 CTAs/SM, v2 fragment loads ----------
// C[R,Nc] = A[R,Kd] @ Bt[Nc,Kd]^T; A/Bt stored k-permuted. 128x128 tile,
// KTILE=16, 3-stage cp.async, one __syncthreads per iteration.
// ACT: 0 plain out, 1 gelu + permuted store (hbuf), 2 final combine.
#define KTILE   16
#define PITCH   24                          // floats/row: 16 data + 8 pad (stride%32=24 banks)
#define TILE_B  (128 * PITCH * 4)           // 12288 bytes
#define STAGE_B (2 * TILE_B)                // 24576
#define STAGES  3
#define SM_TOTAL (STAGES * STAGE_B)         // 73728 bytes -> 2 CTAs/SM

#define CPA_COMMIT() asm volatile("cp.async.commit_group;" ::: "memory")
#define CPA_WAIT1()  asm volatile("cp.async.wait_group 1;" ::: "memory")

__device__ __forceinline__ uint32_t smem_u32(const void* p) {
    uint32_t a;
    asm("{ .reg .u64 t; cvta.to.shared.u64 t, %1; cvt.u32.u64 %0, t; }" : "=r"(a) : "l"(p));
    return a;
}

// one 128x16 tile: 512 x 16B chunks, 2 per thread
__device__ __forceinline__ void load_tile(uint32_t sbase, const float* gbase, int ld) {
    int t = threadIdx.x;
#pragma unroll
    for (int i = 0; i < 2; i++) {
        int idx = t + i * 256;
        int r = idx >> 2, c = idx & 3;
        uint32_t so = sbase + (uint32_t)(r * (PITCH * 4) + c * 16);
        const float* gp = gbase + (size_t)r * ld + c * 4;
        asm volatile("cp.async.cg.shared.global [%0], [%1], 16;" :: "r"(so), "l"(gp));
    }
}

__device__ __forceinline__ void mma_tf32(float* d, uint32_t a0, uint32_t a1, uint32_t a2,
                                         uint32_t a3, uint32_t b0, uint32_t b1) {
    asm volatile(
        "mma.sync.aligned.m16n8k8.row.col.f32.tf32.tf32.f32 "
        "{%0,%1,%2,%3}, {%4,%5,%6,%7}, {%8,%9}, {%0,%1,%2,%3};"
        : "+f"(d[0]), "+f"(d[1]), "+f"(d[2]), "+f"(d[3])
        : "r"(a0), "r"(a1), "r"(a2), "r"(a3), "r"(b0), "r"(b1));
}

template <int ACT>
__global__ __launch_bounds__(256, 2)
void mma_gemm(const float* __restrict__ A, const float* __restrict__ Bt,
              const float* __restrict__ bias, float* __restrict__ C,
              int Kd, int Nc,
              const float* __restrict__ gbuf, const float* __restrict__ ptb,
              const int* __restrict__ pvm) {
    extern __shared__ char smem[];
    uint32_t sb = smem_u32(smem);
    int tid = threadIdx.x, wid = tid >> 5, lane = tid & 31;
    int wm = wid & 1, wn = wid >> 1;              // 2x4 warp grid, warp tile 64x32
    int g = lane >> 2, i4 = lane & 3;
    int row0 = blockIdx.y * 128, col0 = blockIdx.x * 128;

    const int NK = Kd / KTILE;
    const float* Ag = A  + (size_t)row0 * Kd;
    const float* Bg = Bt + (size_t)col0 * Kd;

    // prologue: stages 0,1
#pragma unroll
    for (int p = 0; p < 2; p++) {
        load_tile(sb + p * STAGE_B,          Ag + p * KTILE, Kd);
        load_tile(sb + p * STAGE_B + TILE_B, Bg + p * KTILE, Kd);
        CPA_COMMIT();
    }

    float acc[4][4][4];
#pragma unroll
    for (int mf = 0; mf < 4; mf++)
#pragma unroll
        for (int nf = 0; nf < 4; nf++)
#pragma unroll
            for (int e = 0; e < 4; e++) acc[mf][nf][e] = 0.0f;

    // per-warp smem base offsets (in floats)
    for (int kt = 0; kt < NK; kt++) {
        CPA_WAIT1();                 // tile kt resident (this thread)
        __syncthreads();             // all threads' copies visible; stage (kt-1)%3 fully consumed
        if (kt + 2 < NK) {
            int st = (kt + 2) % STAGES;
            load_tile(sb + st * STAGE_B,          Ag + (size_t)(kt + 2) * KTILE, Kd);
            load_tile(sb + st * STAGE_B + TILE_B, Bg + (size_t)(kt + 2) * KTILE, Kd);
        }
        CPA_COMMIT();

        int s = kt % STAGES;
        const float* As = (const float*)(smem + s * STAGE_B);
        const float* Bs = (const float*)(smem + s * STAGE_B + TILE_B);
#pragma unroll
        for (int ks = 0; ks < 2; ks++) {
            int kc = ks * 8 + 2 * i4;           // permuted col: pair (k, k+4)
            float2 alo[4], ahi[4], bf[4];
#pragma unroll
            for (int mf = 0; mf < 4; mf++) {
                const float* base = As + (wm * 64 + mf * 16 + g) * PITCH + kc;
                alo[mf] = *(const float2*)base;
                ahi[mf] = *(const float2*)(base + 8 * PITCH);
            }
#pragma unroll
            for (int nf = 0; nf < 4; nf++)
                bf[nf] = *(const float2*)(Bs + (wn * 32 + nf * 8 + g) * PITCH + kc);
#pragma unroll
            for (int mf = 0; mf < 4; mf++)
#pragma unroll
                for (int nf = 0; nf < 4; nf++)
                    mma_tf32(acc[mf][nf],
                             __float_as_uint(alo[mf].x), __float_as_uint(ahi[mf].x),
                             __float_as_uint(alo[mf].y), __float_as_uint(ahi[mf].y),
                             __float_as_uint(bf[nf].x),  __float_as_uint(bf[nf].y));
        }
    }

    // epilogue
#pragma unroll
    for (int mf = 0; mf < 4; mf++) {
        int r_lo = row0 + wm * 64 + mf * 16 + g;
#pragma unroll
        for (int nf = 0; nf < 4; nf++) {
            int col = col0 + wn * 32 + nf * 8 + i4 * 2;
            float b0 = bias[col], b1 = bias[col + 1];
#pragma unroll
            for (int h = 0; h < 2; h++) {
                int row = r_lo + h * 8;
                float v0 = acc[mf][nf][h * 2 + 0] + b0;
                float v1 = acc[mf][nf][h * 2 + 1] + b1;
                if (ACT == 1) {
                    // gelu + tf32 round + k-permuted store (hbuf is next GEMM's A)
                    v0 = tf32_rne(gelu_f(v0));
                    v1 = tf32_rne(gelu_f(v1));
                    size_t rb = (size_t)row * Nc;
                    int q = qmap(col);           // q(col+1) == q(col)+2
                    C[rb + q]     = v0;
                    C[rb + q + 2] = v1;
                } else {
                    size_t off = (size_t)row * Nc + col;
                    if (ACT == 2) {
                        float2 g4 = *(const float2*)(gbuf + off);
                        float2 p4 = *(const float2*)(ptb + off);
                        float m = pvm[row] ? 1.0f : 0.0f;
                        v0 = (p4.x + sigmoid_f(g4.x) * v0) * m;
                        v1 = (p4.y + sigmoid_f(g4.y) * v1) * m;
                    }
                    *(float2*)(C + off) = make_float2(v0, v1);
                }
            }
        }
    }
}

// ---------------- K3: kNN top-3 + inverse-distance weights ----------------------
__global__ __launch_bounds__(256)
void knn_kernel(const float* __restrict__ pc, const float* __restrict__ ic,
                const int* __restrict__ imask,
                int* __restrict__ knn_idx, float* __restrict__ knn_w) {
    __shared__ float4 cs[Mm];
    int b = blockIdx.x;
    const float INFV = __int_as_float(0x7f800000);
    for (int m = threadIdx.x; m < Mm; m += 256) {
        size_t ci = ((size_t)b * Mm + m) * 3;
        float x = ic[ci], y = ic[ci + 1], z = ic[ci + 2];
        float s2 = imask[b * Mm + m] ? (x * x + y * y + z * z) : INFV;
        cs[m] = make_float4(x, y, z, s2);
    }
    __syncthreads();

    int n = blockIdx.y * 256 + threadIdx.x;
    size_t pidx = (size_t)b * Nn + n;
    float qx = pc[pidx * 3], qy = pc[pidx * 3 + 1], qz = pc[pidx * 3 + 2];
    float q2 = qx * qx + qy * qy + qz * qz;

    float d0 = INFV, d1 = INFV, d2v = INFV;
    int j0 = 0, j1 = 0, j2 = 0;
#pragma unroll 4
    for (int m = 0; m < Mm; m++) {
        float4 c = cs[m];
        float d = fmaxf(q2 + c.w - 2.0f * (qx * c.x + qy * c.y + qz * c.z), 0.0f);
        if (d < d2v) {
            if (d < d1) {
                d2v = d1; j2 = j1;
                if (d < d0) { d1 = d0; j1 = j0; d0 = d; j0 = m; }
                else        { d1 = d;  j1 = m; }
            } else { d2v = d; j2 = m; }
        }
    }
    float w0 = 1.0f / fmaxf(sqrtf(d0),  1e-6f);
    float w1 = 1.0f / fmaxf(sqrtf(d1),  1e-6f);
    float w2 = 1.0f / fmaxf(sqrtf(d2v), 1e-6f);
    float inv = 1.0f / fmaxf(w0 + w1 + w2, 1e-6f);
    size_t base = pidx * 3;
    knn_idx[base + 0] = b * Mm + j0;
    knn_idx[base + 1] = b * Mm + j1;
    knn_idx[base + 2] = b * Mm + j2;
    knn_w[base + 0] = w0 * inv;
    knn_w[base + 1] = w1 * inv;
    knn_w[base + 2] = w2 * inv;
}

// ---------------- K4: gather + concat + LN, tf32, permuted store ----------------
__global__ __launch_bounds__(128)
void fin_ln_kernel(const float* __restrict__ pt, const int* __restrict__ pvm,
                   float* __restrict__ out) {
    int p = blockIdx.x, tid = threadIdx.x;
    float4 v;
    if (tid < 64) {
        v = *(const float4*)&pt[(size_t)p * ODim + tid * 4];
    } else {
        int base = p * 3;
        int i0 = g_knn_idx[base], i1 = g_knn_idx[base + 1], i2 = g_knn_idx[base + 2];
        float w0 = g_knn_w[base], w1 = g_knn_w[base + 1], w2 = g_knn_w[base + 2];
        int o = (tid - 64) * 4;
        float4 f0 = *(const float4*)&g_imgfeat[(size_t)i0 * ODim + o];
        float4 f1 = *(const float4*)&g_imgfeat[(size_t)i1 * ODim + o];
        float4 f2 = *(const float4*)&g_imgfeat[(size_t)i2 * ODim + o];
        float pv = pvm[p] ? 1.0f : 0.0f;
        v.x = (w0 * f0.x + w1 * f1.x + w2 * f2.x) * pv;
        v.y = (w0 * f0.y + w1 * f1.y + w2 * f2.y) * pv;
        v.z = (w0 * f0.z + w1 * f1.z + w2 * f2.z) * pv;
        v.w = (w0 * f0.w + w1 * f1.w + w2 * f2.w) * pv;
    }
    float s  = v.x + v.y + v.z + v.w;
    float ss = v.x * v.x + v.y * v.y + v.z * v.z + v.w * v.w;
    float2 r = block_reduce2(s, ss);
    float mean = r.x * (1.0f / 512.0f);
    float var  = fmaxf(r.y * (1.0f / 512.0f) - mean * mean, 0.0f);
    float rstd = rsqrtf(var + 1e-5f);
    float* orow = out + (size_t)p * 512;
    int c = tid * 4;
    orow[qmap(c + 0)] = tf32_rne((v.x - mean) * rstd);
    orow[qmap(c + 1)] = tf32_rne((v.y - mean) * rstd);
    orow[qmap(c + 2)] = tf32_rne((v.z - mean) * rstd);
    orow[qmap(c + 3)] = tf32_rne((v.w - mean) * rstd);
}

// ---------------- launch ---------------------------------------------------------
extern "C" void kernel_launch(void* const* d_in, const int* in_sizes, int n_in,
                              void* d_out, int out_size) {
    const float* pt      = (const float*)d_in[0];
    const float* pc      = (const float*)d_in[1];
    const float* it      = (const float*)d_in[2];
    const float* icd     = (const float*)d_in[3];
    const int*   pvm     = (const int*)d_in[4];
    const int*   ivm     = (const int*)d_in[5];
    const float* ip_ln_g = (const float*)d_in[6];
    const float* ip_ln_b = (const float*)d_in[7];
    const float* ip_w1   = (const float*)d_in[8];
    const float* ip_b1   = (const float*)d_in[9];
    const float* ip_w2   = (const float*)d_in[10];
    const float* ip_b2   = (const float*)d_in[11];
    const float* g_ln_g  = (const float*)d_in[12];
    const float* g_ln_b  = (const float*)d_in[13];
    const float* g_w1    = (const float*)d_in[14];
    const float* g_b1    = (const float*)d_in[15];
    const float* g_w2    = (const float*)d_in[16];
    const float* g_b2    = (const float*)d_in[17];
    const float* d_ln_g  = (const float*)d_in[18];
    const float* d_ln_b  = (const float*)d_in[19];
    const float* d_w1    = (const float*)d_in[20];
    const float* d_b1    = (const float*)d_in[21];
    const float* d_w2    = (const float*)d_in[22];
    const float* d_b2    = (const float*)d_in[23];
    float* out = (float*)d_out;

    float *xln, *hbuf, *imgf, *finln, *gate, *knnw;
    float *wt_ip1, *wt_g1, *wt_d1, *wt_ip2, *wt_g2, *wt_d2, *bpip, *bpg, *bpd;
    int* knni;
    cudaGetSymbolAddress((void**)&xln,    g_xln);
    cudaGetSymbolAddress((void**)&hbuf,   g_hbuf);
    cudaGetSymbolAddress((void**)&imgf,   g_imgfeat);
    cudaGetSymbolAddress((void**)&finln,  g_finln);
    cudaGetSymbolAddress((void**)&gate,   g_gate);
    cudaGetSymbolAddress((void**)&knni,   g_knn_idx);
    cudaGetSymbolAddress((void**)&knnw,   g_knn_w);
    cudaGetSymbolAddress((void**)&wt_ip1, g_wt_ip1);
    cudaGetSymbolAddress((void**)&wt_g1,  g_wt_g1);
    cudaGetSymbolAddress((void**)&wt_d1,  g_wt_d1);
    cudaGetSymbolAddress((void**)&wt_ip2, g_wt_ip2);
    cudaGetSymbolAddress((void**)&wt_g2,  g_wt_g2);
    cudaGetSymbolAddress((void**)&wt_d2,  g_wt_d2);
    cudaGetSymbolAddress((void**)&bpip,   g_bp_ip);
    cudaGetSymbolAddress((void**)&bpg,    g_bp_g);
    cudaGetSymbolAddress((void**)&bpd,    g_bp_d);

    cudaFuncSetAttribute(mma_gemm<0>, cudaFuncAttributeMaxDynamicSharedMemorySize, SM_TOTAL);
    cudaFuncSetAttribute(mma_gemm<1>, cudaFuncAttributeMaxDynamicSharedMemorySize, SM_TOTAL);
    cudaFuncSetAttribute(mma_gemm<2>, cudaFuncAttributeMaxDynamicSharedMemorySize, SM_TOTAL);

    // 0) fold LN affine into W1 (+transpose); transpose W2s (tf32, permuted)
    prep_fold_T<<<2, 256>>>(ip_w1, ip_ln_g, ip_ln_b, ip_b1, wt_ip1, bpip, IDim, HDim);
    prep_fold_T<<<2, 256>>>(g_w1,  g_ln_g,  g_ln_b,  g_b1,  wt_g1,  bpg,  2 * ODim, HDim);
    prep_fold_T<<<2, 256>>>(d_w1,  d_ln_g,  d_ln_b,  d_b1,  wt_d1,  bpd,  2 * ODim, HDim);
    transpose_k<<<(HDim * ODim + 255) / 256, 256>>>(ip_w2, wt_ip2, HDim, ODim);
    transpose_k<<<(HDim * ODim + 255) / 256, 256>>>(g_w2,  wt_g2,  HDim, ODim);
    transpose_k<<<(HDim * ODim + 255) / 256, 256>>>(d_w2,  wt_d2,  HDim, ODim);

    // 1) image MLP
    ln_img_kernel<<<ROWS_IMG, 256>>>(it, xln);
    mma_gemm<1><<<dim3(HDim / 128, ROWS_IMG / 128), 256, SM_TOTAL>>>(
        xln, wt_ip1, bpip, hbuf, IDim, HDim, nullptr, nullptr, nullptr);
    mma_gemm<0><<<dim3(ODim / 128, ROWS_IMG / 128), 256, SM_TOTAL>>>(
        hbuf, wt_ip2, ip_b2, imgf, HDim, ODim, nullptr, nullptr, nullptr);

    // 2) kNN top-3
    knn_kernel<<<dim3(Bb, Nn / 256), 256>>>(pc, icd, ivm, knni, knnw);

    // 3) gather+concat+LN -> fin̂ (permuted)
    fin_ln_kernel<<<ROWS_PT, 128>>>(pt, pvm, finln);

    // 4) gate MLP
    mma_gemm<1><<<dim3(HDim / 128, ROWS_PT / 128), 256, SM_TOTAL>>>(
        finln, wt_g1, bpg, hbuf, 2 * ODim, HDim, nullptr, nullptr, nullptr);
    mma_gemm<0><<<dim3(ODim / 128, ROWS_PT / 128), 256, SM_TOTAL>>>(
        hbuf, wt_g2, g_b2, gate, HDim, ODim, nullptr, nullptr, nullptr);

    // 5) delta MLP + fused final combine
    mma_gemm<1><<<dim3(HDim / 128, ROWS_PT / 128), 256, SM_TOTAL>>>(
        finln, wt_d1, bpd, hbuf, 2 * ODim, HDim, nullptr, nullptr, nullptr);
    mma_gemm<2><<<dim3(ODim / 128, ROWS_PT / 128), 256, SM_TOTAL>>>(
        hbuf, wt_d2, d_b2, out, HDim, ODim, gate, pt, pvm);
}

// round 7
// speedup vs baseline: 2.5547x; 1.1721x over previous
#include <cuda_runtime.h>
#include <cuda_fp16.h>
#include <math.h>
#include <stdint.h>

// Problem dims (fixed by the dataset)
#define Bb   16
#define Nn   4096
#define Mm   1024
#define IDim 768
#define HDim 512
#define ODim 256
#define ROWS_IMG (Bb*Mm)   // 16384
#define ROWS_PT  (Bb*Nn)   // 65536

// ---------------- scratch (device globals; no allocation allowed) -------------
__device__ __align__(16) __half g_xln[ROWS_IMG * IDim];        // LN img tokens (fp16, permuted)
__device__ __align__(16) __half g_hbuf[ROWS_PT * HDim];        // hidden (fp16, permuted)
__device__ __align__(16) float g_imgfeat[ROWS_IMG * ODim];     // image MLP out (fp32 plain)
__device__ __align__(16) __half g_finln[ROWS_PT * (2 * ODim)]; // fin̂ (fp16, permuted)
__device__ __align__(16) float g_gate[ROWS_PT * ODim];         // gate pre-sigmoid (fp32)
__device__ int   g_knn_idx[ROWS_PT * 3];
__device__ float g_knn_w[ROWS_PT * 3];
// transposed (LN-folded for layer-1) weights: [N,K] K-major, fp16, permuted
__device__ __align__(16) __half g_wt_ip1[HDim * IDim];
__device__ __align__(16) __half g_wt_g1[HDim * (2*ODim)];
__device__ __align__(16) __half g_wt_d1[HDim * (2*ODim)];
__device__ __align__(16) __half g_wt_ip2[ODim * HDim];
__device__ __align__(16) __half g_wt_g2[ODim * HDim];
__device__ __align__(16) __half g_wt_d2[ODim * HDim];
__device__ float g_bp_ip[HDim];
__device__ float g_bp_g[HDim];
__device__ float g_bp_d[HDim];

// ---------------- helpers ------------------------------------------------------
// k-pair permutation inside each 16-wide k group: pair p=(k>>1)&7 goes to slot
// q = 2*(p&3) | (p>>2). A thread's fragment pairs (p, p+4) become adjacent 8B.
__device__ __host__ __forceinline__ int permk(int k) {
    int p = (k >> 1) & 7;
    int q = ((p & 3) << 1) | (p >> 2);
    return (k & ~15) | (q << 1) | (k & 1);
}
__device__ __forceinline__ float gelu_f(float x) {
    return 0.5f * x * (1.0f + erff(x * 0.70710678118654752f));
}
__device__ __forceinline__ float sigmoid_f(float x) {
    return 1.0f / (1.0f + __expf(-x));
}
__device__ __forceinline__ float2 block_reduce2(float s, float ss) {
    __shared__ float sh[64];
    int lane = threadIdx.x & 31, w = threadIdx.x >> 5;
#pragma unroll
    for (int o = 16; o; o >>= 1) {
        s  += __shfl_down_sync(0xffffffffu, s,  o);
        ss += __shfl_down_sync(0xffffffffu, ss, o);
    }
    if (lane == 0) { sh[w] = s; sh[32 + w] = ss; }
    __syncthreads();
    int nw = (blockDim.x + 31) >> 5;
    if (w == 0) {
        s  = (lane < nw) ? sh[lane]      : 0.0f;
        ss = (lane < nw) ? sh[32 + lane] : 0.0f;
#pragma unroll
        for (int o = 16; o; o >>= 1) {
            s  += __shfl_down_sync(0xffffffffu, s,  o);
            ss += __shfl_down_sync(0xffffffffu, ss, o);
        }
        if (lane == 0) { sh[0] = s; sh[32] = ss; }
    }
    __syncthreads();
    return make_float2(sh[0], sh[32]);
}

// ---------------- K0a: fold LN affine + transpose W1 (fp16, permuted) -----------
__global__ void prep_fold_T(const float* __restrict__ W, const float* __restrict__ g,
                            const float* __restrict__ bln, const float* __restrict__ b1,
                            __half* __restrict__ Wt, float* __restrict__ b1p,
                            int Kd, int Nc) {
    int n = blockIdx.x * blockDim.x + threadIdx.x;
    if (n >= Nc) return;
    float acc = b1[n];
    for (int k = 0; k < Kd; k++) {
        float w = W[(size_t)k * Nc + n];
        Wt[(size_t)n * Kd + permk(k)] = __float2half_rn(g[k] * w);
        acc += bln[k] * w;
    }
    b1p[n] = acc;
}
// ---------------- K0b: transpose (fp16, permuted) -------------------------------
__global__ void transpose_k(const float* __restrict__ W, __half* __restrict__ Wt,
                            int Kd, int Nc) {
    int idx = blockIdx.x * blockDim.x + threadIdx.x;
    if (idx >= Kd * Nc) return;
    int k = idx / Nc, n = idx % Nc;
    Wt[(size_t)n * Kd + permk(k)] = __float2half_rn(W[idx]);
}

// ---------------- K1: LN (normalize only), fp16 permuted store ------------------
__global__ void ln_img_kernel(const float* __restrict__ x, __half* __restrict__ y) {
    int row = blockIdx.x, tid = threadIdx.x;
    const float* xr = x + (size_t)row * IDim;
    float v0 = xr[tid], v1 = xr[tid + 256], v2 = xr[tid + 512];
    float s = v0 + v1 + v2;
    float ss = v0 * v0 + v1 * v1 + v2 * v2;
    float2 r = block_reduce2(s, ss);
    float mean = r.x * (1.0f / 768.0f);
    float var  = fmaxf(r.y * (1.0f / 768.0f) - mean * mean, 0.0f);
    float rstd = rsqrtf(var + 1e-5f);
    __half* yr = y + (size_t)row * IDim;
    yr[permk(tid)]       = __float2half_rn((v0 - mean) * rstd);
    yr[permk(tid + 256)] = __float2half_rn((v1 - mean) * rstd);
    yr[permk(tid + 512)] = __float2half_rn((v2 - mean) * rstd);
}

// ---------------- K2: fp16 m16n8k16 mma.sync GEMM -------------------------------
// C[R,Nc] = A[R,Kd] @ Bt[Nc,Kd]^T; A/Bt fp16, k-permuted. 128x128 tile,
// KTILE=32 (fp16), 3-stage cp.async, 2 CTAs/SM.
// ACT: 0 fp32 out, 1 gelu -> fp16 permuted out (hbuf), 2 final combine fp32 out.
#define KTILE   32
#define PITCHB  96                           // bytes/row: 64 data + 32 pad (bank-bijective)
#define TILE_B  (128 * PITCHB)               // 12288 bytes
#define STAGE_B (2 * TILE_B)                 // 24576
#define STAGES  3
#define SM_TOTAL (STAGES * STAGE_B)          // 73728 -> 2 CTAs/SM

#define CPA_COMMIT() asm volatile("cp.async.commit_group;" ::: "memory")
#define CPA_WAIT1()  asm volatile("cp.async.wait_group 1;" ::: "memory")

__device__ __forceinline__ uint32_t smem_u32(const void* p) {
    uint32_t a;
    asm("{ .reg .u64 t; cvta.to.shared.u64 t, %1; cvt.u32.u64 %0, t; }" : "=r"(a) : "l"(p));
    return a;
}

// one 128x32(fp16) tile: 128 rows x 64B = 512 x 16B chunks, 2 per thread
__device__ __forceinline__ void load_tile(uint32_t sbase, const __half* gbase, int ld) {
    int t = threadIdx.x;
#pragma unroll
    for (int i = 0; i < 2; i++) {
        int idx = t + i * 256;
        int r = idx >> 2, c = idx & 3;
        uint32_t so = sbase + (uint32_t)(r * PITCHB + c * 16);
        const __half* gp = gbase + (size_t)r * ld + c * 8;
        asm volatile("cp.async.cg.shared.global [%0], [%1], 16;" :: "r"(so), "l"(gp));
    }
}

__device__ __forceinline__ void mma_f16(float* d, uint32_t a0, uint32_t a1, uint32_t a2,
                                        uint32_t a3, uint32_t b0, uint32_t b1) {
    asm volatile(
        "mma.sync.aligned.m16n8k16.row.col.f32.f16.f16.f32 "
        "{%0,%1,%2,%3}, {%4,%5,%6,%7}, {%8,%9}, {%0,%1,%2,%3};"
        : "+f"(d[0]), "+f"(d[1]), "+f"(d[2]), "+f"(d[3])
        : "r"(a0), "r"(a1), "r"(a2), "r"(a3), "r"(b0), "r"(b1));
}

template <int ACT>
__global__ __launch_bounds__(256, 2)
void mma_gemm(const __half* __restrict__ A, const __half* __restrict__ Bt,
              const float* __restrict__ bias, void* __restrict__ Cv,
              int Kd, int Nc,
              const float* __restrict__ gbuf, const float* __restrict__ ptb,
              const int* __restrict__ pvm) {
    extern __shared__ char smem[];
    uint32_t sb = smem_u32(smem);
    int tid = threadIdx.x, wid = tid >> 5, lane = tid & 31;
    int wm = wid & 1, wn = wid >> 1;              // 2x4 warp grid, warp tile 64x32
    int g = lane >> 2, i4 = lane & 3;
    int row0 = blockIdx.y * 128, col0 = blockIdx.x * 128;

    const int NK = Kd / KTILE;
    const __half* Ag = A  + (size_t)row0 * Kd;
    const __half* Bg = Bt + (size_t)col0 * Kd;

    // prologue: stages 0,1
#pragma unroll
    for (int p = 0; p < 2; p++) {
        load_tile(sb + p * STAGE_B,          Ag + p * KTILE, Kd);
        load_tile(sb + p * STAGE_B + TILE_B, Bg + p * KTILE, Kd);
        CPA_COMMIT();
    }

    float acc[4][4][4];
#pragma unroll
    for (int mf = 0; mf < 4; mf++)
#pragma unroll
        for (int nf = 0; nf < 4; nf++)
#pragma unroll
            for (int e = 0; e < 4; e++) acc[mf][nf][e] = 0.0f;

    for (int kt = 0; kt < NK; kt++) {
        CPA_WAIT1();
        __syncthreads();
        if (kt + 2 < NK) {
            int st = (kt + 2) % STAGES;
            load_tile(sb + st * STAGE_B,          Ag + (size_t)(kt + 2) * KTILE, Kd);
            load_tile(sb + st * STAGE_B + TILE_B, Bg + (size_t)(kt + 2) * KTILE, Kd);
        }
        CPA_COMMIT();

        int s = kt % STAGES;
        const char* As = smem + s * STAGE_B;
        const char* Bs = smem + s * STAGE_B + TILE_B;
#pragma unroll
        for (int ks = 0; ks < 2; ks++) {
            int kb = ks * 32 + 8 * i4;            // byte offset: thread's adjacent pair group
            uint2 alo[4], ahi[4], bf[4];
#pragma unroll
            for (int mf = 0; mf < 4; mf++) {
                const char* base = As + (wm * 64 + mf * 16 + g) * PITCHB + kb;
                alo[mf] = *(const uint2*)base;                  // row g:   (a0, a2)
                ahi[mf] = *(const uint2*)(base + 8 * PITCHB);   // row g+8: (a1, a3)
            }
#pragma unroll
            for (int nf = 0; nf < 4; nf++)
                bf[nf] = *(const uint2*)(Bs + (wn * 32 + nf * 8 + g) * PITCHB + kb);
#pragma unroll
            for (int mf = 0; mf < 4; mf++)
#pragma unroll
                for (int nf = 0; nf < 4; nf++)
                    mma_f16(acc[mf][nf],
                            alo[mf].x, ahi[mf].x, alo[mf].y, ahi[mf].y,
                            bf[nf].x,  bf[nf].y);
        }
    }

    // epilogue
#pragma unroll
    for (int mf = 0; mf < 4; mf++) {
        int r_lo = row0 + wm * 64 + mf * 16 + g;
#pragma unroll
        for (int nf = 0; nf < 4; nf++) {
            int col = col0 + wn * 32 + nf * 8 + i4 * 2;
            float b0 = bias[col], b1 = bias[col + 1];
#pragma unroll
            for (int h = 0; h < 2; h++) {
                int row = r_lo + h * 8;
                float v0 = acc[mf][nf][h * 2 + 0] + b0;
                float v1 = acc[mf][nf][h * 2 + 1] + b1;
                if (ACT == 1) {
                    // gelu -> fp16 permuted store (hbuf is next GEMM's A)
                    __half2 o;
                    o.x = __float2half_rn(gelu_f(v0));
                    o.y = __float2half_rn(gelu_f(v1));
                    __half* C = (__half*)Cv;
                    *(__half2*)(C + (size_t)row * Nc + permk(col)) = o;
                } else {
                    float* C = (float*)Cv;
                    size_t off = (size_t)row * Nc + col;
                    if (ACT == 2) {
                        float2 g4 = *(const float2*)(gbuf + off);
                        float2 p4 = *(const float2*)(ptb + off);
                        float m = pvm[row] ? 1.0f : 0.0f;
                        v0 = (p4.x + sigmoid_f(g4.x) * v0) * m;
                        v1 = (p4.y + sigmoid_f(g4.y) * v1) * m;
                    }
                    *(float2*)(C + off) = make_float2(v0, v1);
                }
            }
        }
    }
}

// ---------------- K3: kNN top-3 + inverse-distance weights ----------------------
__global__ __launch_bounds__(256)
void knn_kernel(const float* __restrict__ pc, const float* __restrict__ ic,
                const int* __restrict__ imask,
                int* __restrict__ knn_idx, float* __restrict__ knn_w) {
    __shared__ float4 cs[Mm];
    int b = blockIdx.x;
    const float INFV = __int_as_float(0x7f800000);
    for (int m = threadIdx.x; m < Mm; m += 256) {
        size_t ci = ((size_t)b * Mm + m) * 3;
        float x = ic[ci], y = ic[ci + 1], z = ic[ci + 2];
        float s2 = imask[b * Mm + m] ? (x * x + y * y + z * z) : INFV;
        cs[m] = make_float4(x, y, z, s2);
    }
    __syncthreads();

    int n = blockIdx.y * 256 + threadIdx.x;
    size_t pidx = (size_t)b * Nn + n;
    float qx = pc[pidx * 3], qy = pc[pidx * 3 + 1], qz = pc[pidx * 3 + 2];
    float q2 = qx * qx + qy * qy + qz * qz;

    float d0 = INFV, d1 = INFV, d2v = INFV;
    int j0 = 0, j1 = 0, j2 = 0;
#pragma unroll 4
    for (int m = 0; m < Mm; m++) {
        float4 c = cs[m];
        float d = fmaxf(q2 + c.w - 2.0f * (qx * c.x + qy * c.y + qz * c.z), 0.0f);
        if (d < d2v) {
            if (d < d1) {
                d2v = d1; j2 = j1;
                if (d < d0) { d1 = d0; j1 = j0; d0 = d; j0 = m; }
                else        { d1 = d;  j1 = m; }
            } else { d2v = d; j2 = m; }
        }
    }
    float w0 = 1.0f / fmaxf(sqrtf(d0),  1e-6f);
    float w1 = 1.0f / fmaxf(sqrtf(d1),  1e-6f);
    float w2 = 1.0f / fmaxf(sqrtf(d2v), 1e-6f);
    float inv = 1.0f / fmaxf(w0 + w1 + w2, 1e-6f);
    size_t base = pidx * 3;
    knn_idx[base + 0] = b * Mm + j0;
    knn_idx[base + 1] = b * Mm + j1;
    knn_idx[base + 2] = b * Mm + j2;
    knn_w[base + 0] = w0 * inv;
    knn_w[base + 1] = w1 * inv;
    knn_w[base + 2] = w2 * inv;
}

// ---------------- K4: gather + concat + LN, fp16 permuted store -----------------
__global__ __launch_bounds__(128)
void fin_ln_kernel(const float* __restrict__ pt, const int* __restrict__ pvm,
                   __half* __restrict__ out) {
    int p = blockIdx.x, tid = threadIdx.x;
    float4 v;
    if (tid < 64) {
        v = *(const float4*)&pt[(size_t)p * ODim + tid * 4];
    } else {
        int base = p * 3;
        int i0 = g_knn_idx[base], i1 = g_knn_idx[base + 1], i2 = g_knn_idx[base + 2];
        float w0 = g_knn_w[base], w1 = g_knn_w[base + 1], w2 = g_knn_w[base + 2];
        int o = (tid - 64) * 4;
        float4 f0 = *(const float4*)&g_imgfeat[(size_t)i0 * ODim + o];
        float4 f1 = *(const float4*)&g_imgfeat[(size_t)i1 * ODim + o];
        float4 f2 = *(const float4*)&g_imgfeat[(size_t)i2 * ODim + o];
        float pv = pvm[p] ? 1.0f : 0.0f;
        v.x = (w0 * f0.x + w1 * f1.x + w2 * f2.x) * pv;
        v.y = (w0 * f0.y + w1 * f1.y + w2 * f2.y) * pv;
        v.z = (w0 * f0.z + w1 * f1.z + w2 * f2.z) * pv;
        v.w = (w0 * f0.w + w1 * f1.w + w2 * f2.w) * pv;
    }
    float s  = v.x + v.y + v.z + v.w;
    float ss = v.x * v.x + v.y * v.y + v.z * v.z + v.w * v.w;
    float2 r = block_reduce2(s, ss);
    float mean = r.x * (1.0f / 512.0f);
    float var  = fmaxf(r.y * (1.0f / 512.0f) - mean * mean, 0.0f);
    float rstd = rsqrtf(var + 1e-5f);
    __half* orow = out + (size_t)p * 512;
    int c = tid * 4;
    __half2 o01, o23;
    o01.x = __float2half_rn((v.x - mean) * rstd);
    o01.y = __float2half_rn((v.y - mean) * rstd);
    o23.x = __float2half_rn((v.z - mean) * rstd);
    o23.y = __float2half_rn((v.w - mean) * rstd);
    *(__half2*)(orow + permk(c))     = o01;
    *(__half2*)(orow + permk(c + 2)) = o23;
}

// ---------------- launch ---------------------------------------------------------
extern "C" void kernel_launch(void* const* d_in, const int* in_sizes, int n_in,
                              void* d_out, int out_size) {
    const float* pt      = (const float*)d_in[0];
    const float* pc      = (const float*)d_in[1];
    const float* it      = (const float*)d_in[2];
    const float* icd     = (const float*)d_in[3];
    const int*   pvm     = (const int*)d_in[4];
    const int*   ivm     = (const int*)d_in[5];
    const float* ip_ln_g = (const float*)d_in[6];
    const float* ip_ln_b = (const float*)d_in[7];
    const float* ip_w1   = (const float*)d_in[8];
    const float* ip_b1   = (const float*)d_in[9];
    const float* ip_w2   = (const float*)d_in[10];
    const float* ip_b2   = (const float*)d_in[11];
    const float* g_ln_g  = (const float*)d_in[12];
    const float* g_ln_b  = (const float*)d_in[13];
    const float* g_w1    = (const float*)d_in[14];
    const float* g_b1    = (const float*)d_in[15];
    const float* g_w2    = (const float*)d_in[16];
    const float* g_b2    = (const float*)d_in[17];
    const float* d_ln_g  = (const float*)d_in[18];
    const float* d_ln_b  = (const float*)d_in[19];
    const float* d_w1    = (const float*)d_in[20];
    const float* d_b1    = (const float*)d_in[21];
    const float* d_w2    = (const float*)d_in[22];
    const float* d_b2    = (const float*)d_in[23];
    float* out = (float*)d_out;

    __half *xln, *hbuf, *finln, *wt_ip1, *wt_g1, *wt_d1, *wt_ip2, *wt_g2, *wt_d2;
    float *imgf, *gate, *knnw, *bpip, *bpg, *bpd;
    int* knni;
    cudaGetSymbolAddress((void**)&xln,    g_xln);
    cudaGetSymbolAddress((void**)&hbuf,   g_hbuf);
    cudaGetSymbolAddress((void**)&imgf,   g_imgfeat);
    cudaGetSymbolAddress((void**)&finln,  g_finln);
    cudaGetSymbolAddress((void**)&gate,   g_gate);
    cudaGetSymbolAddress((void**)&knni,   g_knn_idx);
    cudaGetSymbolAddress((void**)&knnw,   g_knn_w);
    cudaGetSymbolAddress((void**)&wt_ip1, g_wt_ip1);
    cudaGetSymbolAddress((void**)&wt_g1,  g_wt_g1);
    cudaGetSymbolAddress((void**)&wt_d1,  g_wt_d1);
    cudaGetSymbolAddress((void**)&wt_ip2, g_wt_ip2);
    cudaGetSymbolAddress((void**)&wt_g2,  g_wt_g2);
    cudaGetSymbolAddress((void**)&wt_d2,  g_wt_d2);
    cudaGetSymbolAddress((void**)&bpip,   g_bp_ip);
    cudaGetSymbolAddress((void**)&bpg,    g_bp_g);
    cudaGetSymbolAddress((void**)&bpd,    g_bp_d);

    cudaFuncSetAttribute(mma_gemm<0>, cudaFuncAttributeMaxDynamicSharedMemorySize, SM_TOTAL);
    cudaFuncSetAttribute(mma_gemm<1>, cudaFuncAttributeMaxDynamicSharedMemorySize, SM_TOTAL);
    cudaFuncSetAttribute(mma_gemm<2>, cudaFuncAttributeMaxDynamicSharedMemorySize, SM_TOTAL);

    // Launch order arranged so ncu (-s 5 -c 1) captures launch #5 = the img L1 GEMM.
    prep_fold_T<<<2, 256>>>(ip_w1, ip_ln_g, ip_ln_b, ip_b1, wt_ip1, bpip, IDim, HDim);  // 0
    transpose_k<<<(HDim * ODim + 255) / 256, 256>>>(ip_w2, wt_ip2, HDim, ODim);         // 1
    prep_fold_T<<<2, 256>>>(g_w1, g_ln_g, g_ln_b, g_b1, wt_g1, bpg, 2 * ODim, HDim);    // 2
    prep_fold_T<<<2, 256>>>(d_w1, d_ln_g, d_ln_b, d_b1, wt_d1, bpd, 2 * ODim, HDim);    // 3
    ln_img_kernel<<<ROWS_IMG, 256>>>(it, xln);                                          // 4

    // 5: image MLP layer 1 (profiled launch)
    mma_gemm<1><<<dim3(HDim / 128, ROWS_IMG / 128), 256, SM_TOTAL>>>(
        xln, wt_ip1, bpip, hbuf, IDim, HDim, nullptr, nullptr, nullptr);
    // 6: image MLP layer 2
    mma_gemm<0><<<dim3(ODim / 128, ROWS_IMG / 128), 256, SM_TOTAL>>>(
        hbuf, wt_ip2, ip_b2, imgf, HDim, ODim, nullptr, nullptr, nullptr);

    transpose_k<<<(HDim * ODim + 255) / 256, 256>>>(g_w2, wt_g2, HDim, ODim);           // 7
    transpose_k<<<(HDim * ODim + 255) / 256, 256>>>(d_w2, wt_d2, HDim, ODim);           // 8

    knn_kernel<<<dim3(Bb, Nn / 256), 256>>>(pc, icd, ivm, knni, knnw);                  // 9
    fin_ln_kernel<<<ROWS_PT, 128>>>(pt, pvm, finln);                                    // 10

    // gate MLP
    mma_gemm<1><<<dim3(HDim / 128, ROWS_PT / 128), 256, SM_TOTAL>>>(
        finln, wt_g1, bpg, hbuf, 2 * ODim, HDim, nullptr, nullptr, nullptr);
    mma_gemm<0><<<dim3(ODim / 128, ROWS_PT / 128), 256, SM_TOTAL>>>(
        hbuf, wt_g2, g_b2, gate, HDim, ODim, nullptr, nullptr, nullptr);

    // delta MLP + fused final combine
    mma_gemm<1><<<dim3(HDim / 128, ROWS_PT / 128), 256, SM_TOTAL>>>(
        finln, wt_d1, bpd, hbuf, 2 * ODim, HDim, nullptr, nullptr, nullptr);
    mma_gemm<2><<<dim3(ODim / 128, ROWS_PT / 128), 256, SM_TOTAL>>>(
        hbuf, wt_d2, d_b2, out, HDim, ODim, gate, pt, pvm);
}

// round 8
// speedup vs baseline: 4.3928x; 1.7195x over previous
#include <cuda_runtime.h>
#include <cuda_fp16.h>
#include <math.h>
#include <stdint.h>

// Problem dims (fixed by the dataset)
#define Bb   16
#define Nn   4096
#define Mm   1024
#define IDim 768
#define HDim 512
#define ODim 256
#define ROWS_IMG (Bb*Mm)   // 16384
#define ROWS_PT  (Bb*Nn)   // 65536

// ---------------- scratch (device globals; no allocation allowed) -------------
__device__ __align__(16) __half g_xln[ROWS_IMG * IDim];          // LN img tokens (fp16, permuted)
__device__ __align__(16) __half g_hbuf[ROWS_PT * 2 * HDim];      // hidden (fp16, permuted; up to 1024 wide)
__device__ __align__(16) float g_imgfeat[ROWS_IMG * ODim];       // image MLP out (fp32 plain)
__device__ __align__(16) __half g_finln[ROWS_PT * (2 * ODim)];   // fin̂ (fp16, permuted)
__device__ __align__(16) float g_gate[ROWS_PT * ODim];           // gate pre-sigmoid (fp32)
__device__ int   g_knn_idx[ROWS_PT * 3];
__device__ float g_knn_w[ROWS_PT * 3];
// transposed (LN-folded) weights: [N,K] K-major, fp16, permuted
__device__ __align__(16) __half g_wt_ip1[HDim * IDim];
__device__ __align__(16) __half g_wt_gd1[(2 * HDim) * HDim];     // fused gate|delta layer-1
__device__ __align__(16) __half g_wt_ip2[ODim * HDim];
__device__ __align__(16) __half g_wt_g2[ODim * HDim];
__device__ __align__(16) __half g_wt_d2[ODim * HDim];
__device__ float g_bp_ip[HDim];
__device__ float g_bp_gd[2 * HDim];                              // fused gate|delta bias

// ---------------- helpers ------------------------------------------------------
// k-pair permutation inside each 16-wide k group: pair p=(k>>1)&7 goes to slot
// q = 2*(p&3) | (p>>2). A thread's fragment pairs (p, p+4) become adjacent 8B.
__device__ __host__ __forceinline__ int permk(int k) {
    int p = (k >> 1) & 7;
    int q = ((p & 3) << 1) | (p >> 2);
    return (k & ~15) | (q << 1) | (k & 1);
}
__device__ __forceinline__ float gelu_f(float x) {
    return 0.5f * x * (1.0f + erff(x * 0.70710678118654752f));
}
__device__ __forceinline__ float sigmoid_f(float x) {
    return 1.0f / (1.0f + __expf(-x));
}
__device__ __forceinline__ float2 block_reduce2(float s, float ss) {
    __shared__ float sh[64];
    int lane = threadIdx.x & 31, w = threadIdx.x >> 5;
#pragma unroll
    for (int o = 16; o; o >>= 1) {
        s  += __shfl_down_sync(0xffffffffu, s,  o);
        ss += __shfl_down_sync(0xffffffffu, ss, o);
    }
    if (lane == 0) { sh[w] = s; sh[32 + w] = ss; }
    __syncthreads();
    int nw = (blockDim.x + 31) >> 5;
    if (w == 0) {
        s  = (lane < nw) ? sh[lane]      : 0.0f;
        ss = (lane < nw) ? sh[32 + lane] : 0.0f;
#pragma unroll
        for (int o = 16; o; o >>= 1) {
            s  += __shfl_down_sync(0xffffffffu, s,  o);
            ss += __shfl_down_sync(0xffffffffu, ss, o);
        }
        if (lane == 0) { sh[0] = s; sh[32] = ss; }
    }
    __syncthreads();
    return make_float2(sh[0], sh[32]);
}

// ---------------- K0a: elementwise LN-gain fold + transpose (fp16, permuted) ----
// Wt[n*Kd + permk(k)] = half(gain[k] * W[k*Nc + n]); full grid, coalesced reads.
__global__ void fold_w1(const float* __restrict__ W, const float* __restrict__ gain,
                        __half* __restrict__ Wt, int Kd, int Nc) {
    int idx = blockIdx.x * blockDim.x + threadIdx.x;
    if (idx >= Kd * Nc) return;
    int k = idx / Nc, n = idx % Nc;
    Wt[(size_t)n * Kd + permk(k)] = __float2half_rn(gain[k] * W[idx]);
}
// ---------------- K0b: bias fold: b1p[n] = b1[n] + sum_k bln[k]*W[k,n] -----------
// block = 64 n x 4 k-strips; coalesced reads, parallel over Nc/64 blocks.
__global__ void fold_b1(const float* __restrict__ W, const float* __restrict__ bln,
                        const float* __restrict__ b1, float* __restrict__ b1p,
                        int Kd, int Nc) {
    __shared__ float sh[256];
    int nl = threadIdx.x & 63, ks = threadIdx.x >> 6;
    int n = blockIdx.x * 64 + nl;
    float acc = 0.0f;
    for (int k = ks; k < Kd; k += 4)
        acc += bln[k] * W[(size_t)k * Nc + n];
    sh[threadIdx.x] = acc;
    __syncthreads();
    if (ks == 0)
        b1p[n] = b1[n] + sh[nl] + sh[64 + nl] + sh[128 + nl] + sh[192 + nl];
}
// ---------------- K0c: plain transpose (fp16, permuted) -------------------------
__global__ void transpose_k(const float* __restrict__ W, __half* __restrict__ Wt,
                            int Kd, int Nc) {
    int idx = blockIdx.x * blockDim.x + threadIdx.x;
    if (idx >= Kd * Nc) return;
    int k = idx / Nc, n = idx % Nc;
    Wt[(size_t)n * Kd + permk(k)] = __float2half_rn(W[idx]);
}

// ---------------- K1: LN (normalize only), fp16 permuted store ------------------
__global__ void ln_img_kernel(const float* __restrict__ x, __half* __restrict__ y) {
    int row = blockIdx.x, tid = threadIdx.x;
    const float* xr = x + (size_t)row * IDim;
    float v0 = xr[tid], v1 = xr[tid + 256], v2 = xr[tid + 512];
    float s = v0 + v1 + v2;
    float ss = v0 * v0 + v1 * v1 + v2 * v2;
    float2 r = block_reduce2(s, ss);
    float mean = r.x * (1.0f / 768.0f);
    float var  = fmaxf(r.y * (1.0f / 768.0f) - mean * mean, 0.0f);
    float rstd = rsqrtf(var + 1e-5f);
    __half* yr = y + (size_t)row * IDim;
    yr[permk(tid)]       = __float2half_rn((v0 - mean) * rstd);
    yr[permk(tid + 256)] = __float2half_rn((v1 - mean) * rstd);
    yr[permk(tid + 512)] = __float2half_rn((v2 - mean) * rstd);
}

// ---------------- K2: fp16 m16n8k16 mma.sync GEMM -------------------------------
// C[R,Nc] = A[R,Kd] @ Bt[Nc,Kd]^T; A row stride lda. 128x128 tile, KTILE=32,
// 3-stage cp.async, 2 CTAs/SM.
// ACT: 0 fp32 out, 1 gelu -> fp16 permuted out (hbuf), 2 final combine fp32 out.
#define KTILE   32
#define PITCHB  96                           // bytes/row: 64 data + 32 pad
#define TILE_B  (128 * PITCHB)               // 12288 bytes
#define STAGE_B (2 * TILE_B)                 // 24576
#define STAGES  3
#define SM_TOTAL (STAGES * STAGE_B)          // 73728 -> 2 CTAs/SM

#define CPA_COMMIT() asm volatile("cp.async.commit_group;" ::: "memory")
#define CPA_WAIT1()  asm volatile("cp.async.wait_group 1;" ::: "memory")

__device__ __forceinline__ uint32_t smem_u32(const void* p) {
    uint32_t a;
    asm("{ .reg .u64 t; cvta.to.shared.u64 t, %1; cvt.u32.u64 %0, t; }" : "=r"(a) : "l"(p));
    return a;
}

// one 128x32(fp16) tile: 128 rows x 64B = 512 x 16B chunks, 2 per thread
__device__ __forceinline__ void load_tile(uint32_t sbase, const __half* gbase, int ld) {
    int t = threadIdx.x;
#pragma unroll
    for (int i = 0; i < 2; i++) {
        int idx = t + i * 256;
        int r = idx >> 2, c = idx & 3;
        uint32_t so = sbase + (uint32_t)(r * PITCHB + c * 16);
        const __half* gp = gbase + (size_t)r * ld + c * 8;
        asm volatile("cp.async.cg.shared.global [%0], [%1], 16;" :: "r"(so), "l"(gp));
    }
}

__device__ __forceinline__ void mma_f16(float* d, uint32_t a0, uint32_t a1, uint32_t a2,
                                        uint32_t a3, uint32_t b0, uint32_t b1) {
    asm volatile(
        "mma.sync.aligned.m16n8k16.row.col.f32.f16.f16.f32 "
        "{%0,%1,%2,%3}, {%4,%5,%6,%7}, {%8,%9}, {%0,%1,%2,%3};"
        : "+f"(d[0]), "+f"(d[1]), "+f"(d[2]), "+f"(d[3])
        : "r"(a0), "r"(a1), "r"(a2), "r"(a3), "r"(b0), "r"(b1));
}

template <int ACT>
__global__ __launch_bounds__(256, 2)
void mma_gemm(const __half* __restrict__ A, int lda, const __half* __restrict__ Bt,
              const float* __restrict__ bias, void* __restrict__ Cv,
              int Kd, int Nc,
              const float* __restrict__ gbuf, const float* __restrict__ ptb,
              const int* __restrict__ pvm) {
    extern __shared__ char smem[];
    uint32_t sb = smem_u32(smem);
    int tid = threadIdx.x, wid = tid >> 5, lane = tid & 31;
    int wm = wid & 1, wn = wid >> 1;              // 2x4 warp grid, warp tile 64x32
    int g = lane >> 2, i4 = lane & 3;
    int row0 = blockIdx.y * 128, col0 = blockIdx.x * 128;

    const int NK = Kd / KTILE;
    const __half* Ag = A  + (size_t)row0 * lda;
    const __half* Bg = Bt + (size_t)col0 * Kd;

    // prologue: stages 0,1
#pragma unroll
    for (int p = 0; p < 2; p++) {
        load_tile(sb + p * STAGE_B,          Ag + p * KTILE, lda);
        load_tile(sb + p * STAGE_B + TILE_B, Bg + p * KTILE, Kd);
        CPA_COMMIT();
    }

    float acc[4][4][4];
#pragma unroll
    for (int mf = 0; mf < 4; mf++)
#pragma unroll
        for (int nf = 0; nf < 4; nf++)
#pragma unroll
            for (int e = 0; e < 4; e++) acc[mf][nf][e] = 0.0f;

    for (int kt = 0; kt < NK; kt++) {
        CPA_WAIT1();
        __syncthreads();
        if (kt + 2 < NK) {
            int st = (kt + 2) % STAGES;
            load_tile(sb + st * STAGE_B,          Ag + (size_t)(kt + 2) * KTILE, lda);
            load_tile(sb + st * STAGE_B + TILE_B, Bg + (size_t)(kt + 2) * KTILE, Kd);
        }
        CPA_COMMIT();

        int s = kt % STAGES;
        const char* As = smem + s * STAGE_B;
        const char* Bs = smem + s * STAGE_B + TILE_B;
#pragma unroll
        for (int ks = 0; ks < 2; ks++) {
            int kb = ks * 32 + 8 * i4;            // byte offset: thread's adjacent pair group
            uint2 alo[4], ahi[4], bf[4];
#pragma unroll
            for (int mf = 0; mf < 4; mf++) {
                const char* base = As + (wm * 64 + mf * 16 + g) * PITCHB + kb;
                alo[mf] = *(const uint2*)base;                  // row g:   (a0, a2)
                ahi[mf] = *(const uint2*)(base + 8 * PITCHB);   // row g+8: (a1, a3)
            }
#pragma unroll
            for (int nf = 0; nf < 4; nf++)
                bf[nf] = *(const uint2*)(Bs + (wn * 32 + nf * 8 + g) * PITCHB + kb);
#pragma unroll
            for (int mf = 0; mf < 4; mf++)
#pragma unroll
                for (int nf = 0; nf < 4; nf++)
                    mma_f16(acc[mf][nf],
                            alo[mf].x, ahi[mf].x, alo[mf].y, ahi[mf].y,
                            bf[nf].x,  bf[nf].y);
        }
    }

    // epilogue
#pragma unroll
    for (int mf = 0; mf < 4; mf++) {
        int r_lo = row0 + wm * 64 + mf * 16 + g;
#pragma unroll
        for (int nf = 0; nf < 4; nf++) {
            int col = col0 + wn * 32 + nf * 8 + i4 * 2;
            float b0 = bias[col], b1 = bias[col + 1];
#pragma unroll
            for (int h = 0; h < 2; h++) {
                int row = r_lo + h * 8;
                float v0 = acc[mf][nf][h * 2 + 0] + b0;
                float v1 = acc[mf][nf][h * 2 + 1] + b1;
                if (ACT == 1) {
                    // gelu -> fp16 permuted store (hbuf is next GEMM's A)
                    __half2 o;
                    o.x = __float2half_rn(gelu_f(v0));
                    o.y = __float2half_rn(gelu_f(v1));
                    __half* C = (__half*)Cv;
                    *(__half2*)(C + (size_t)row * Nc + permk(col)) = o;
                } else {
                    float* C = (float*)Cv;
                    size_t off = (size_t)row * Nc + col;
                    if (ACT == 2) {
                        float2 g4 = *(const float2*)(gbuf + off);
                        float2 p4 = *(const float2*)(ptb + off);
                        float m = pvm[row] ? 1.0f : 0.0f;
                        v0 = (p4.x + sigmoid_f(g4.x) * v0) * m;
                        v1 = (p4.y + sigmoid_f(g4.y) * v1) * m;
                    }
                    *(float2*)(C + off) = make_float2(v0, v1);
                }
            }
        }
    }
}

// ---------------- K3: kNN top-3 + inverse-distance weights ----------------------
__global__ __launch_bounds__(256)
void knn_kernel(const float* __restrict__ pc, const float* __restrict__ ic,
                const int* __restrict__ imask,
                int* __restrict__ knn_idx, float* __restrict__ knn_w) {
    __shared__ float4 cs[Mm];
    int b = blockIdx.x;
    const float INFV = __int_as_float(0x7f800000);
    for (int m = threadIdx.x; m < Mm; m += 256) {
        size_t ci = ((size_t)b * Mm + m) * 3;
        float x = ic[ci], y = ic[ci + 1], z = ic[ci + 2];
        float s2 = imask[b * Mm + m] ? (x * x + y * y + z * z) : INFV;
        cs[m] = make_float4(x, y, z, s2);
    }
    __syncthreads();

    int n = blockIdx.y * 256 + threadIdx.x;
    size_t pidx = (size_t)b * Nn + n;
    float qx = pc[pidx * 3], qy = pc[pidx * 3 + 1], qz = pc[pidx * 3 + 2];
    float q2 = qx * qx + qy * qy + qz * qz;

    float d0 = INFV, d1 = INFV, d2v = INFV;
    int j0 = 0, j1 = 0, j2 = 0;
#pragma unroll 4
    for (int m = 0; m < Mm; m++) {
        float4 c = cs[m];
        float d = fmaxf(q2 + c.w - 2.0f * (qx * c.x + qy * c.y + qz * c.z), 0.0f);
        if (d < d2v) {
            if (d < d1) {
                d2v = d1; j2 = j1;
                if (d < d0) { d1 = d0; j1 = j0; d0 = d; j0 = m; }
                else        { d1 = d;  j1 = m; }
            } else { d2v = d; j2 = m; }
        }
    }
    float w0 = 1.0f / fmaxf(sqrtf(d0),  1e-6f);
    float w1 = 1.0f / fmaxf(sqrtf(d1),  1e-6f);
    float w2 = 1.0f / fmaxf(sqrtf(d2v), 1e-6f);
    float inv = 1.0f / fmaxf(w0 + w1 + w2, 1e-6f);
    size_t base = pidx * 3;
    knn_idx[base + 0] = b * Mm + j0;
    knn_idx[base + 1] = b * Mm + j1;
    knn_idx[base + 2] = b * Mm + j2;
    knn_w[base + 0] = w0 * inv;
    knn_w[base + 1] = w1 * inv;
    knn_w[base + 2] = w2 * inv;
}

// ---------------- K4: gather + concat + LN, fp16 permuted store -----------------
__global__ __launch_bounds__(128)
void fin_ln_kernel(const float* __restrict__ pt, const int* __restrict__ pvm,
                   __half* __restrict__ out) {
    int p = blockIdx.x, tid = threadIdx.x;
    float4 v;
    if (tid < 64) {
        v = *(const float4*)&pt[(size_t)p * ODim + tid * 4];
    } else {
        int base = p * 3;
        int i0 = g_knn_idx[base], i1 = g_knn_idx[base + 1], i2 = g_knn_idx[base + 2];
        float w0 = g_knn_w[base], w1 = g_knn_w[base + 1], w2 = g_knn_w[base + 2];
        int o = (tid - 64) * 4;
        float4 f0 = *(const float4*)&g_imgfeat[(size_t)i0 * ODim + o];
        float4 f1 = *(const float4*)&g_imgfeat[(size_t)i1 * ODim + o];
        float4 f2 = *(const float4*)&g_imgfeat[(size_t)i2 * ODim + o];
        float pv = pvm[p] ? 1.0f : 0.0f;
        v.x = (w0 * f0.x + w1 * f1.x + w2 * f2.x) * pv;
        v.y = (w0 * f0.y + w1 * f1.y + w2 * f2.y) * pv;
        v.z = (w0 * f0.z + w1 * f1.z + w2 * f2.z) * pv;
        v.w = (w0 * f0.w + w1 * f1.w + w2 * f2.w) * pv;
    }
    float s  = v.x + v.y + v.z + v.w;
    float ss = v.x * v.x + v.y * v.y + v.z * v.z + v.w * v.w;
    float2 r = block_reduce2(s, ss);
    float mean = r.x * (1.0f / 512.0f);
    float var  = fmaxf(r.y * (1.0f / 512.0f) - mean * mean, 0.0f);
    float rstd = rsqrtf(var + 1e-5f);
    __half* orow = out + (size_t)p * 512;
    int c = tid * 4;
    __half2 o01, o23;
    o01.x = __float2half_rn((v.x - mean) * rstd);
    o01.y = __float2half_rn((v.y - mean) * rstd);
    o23.x = __float2half_rn((v.z - mean) * rstd);
    o23.y = __float2half_rn((v.w - mean) * rstd);
    *(__half2*)(orow + permk(c))     = o01;
    *(__half2*)(orow + permk(c + 2)) = o23;
}

// ---------------- launch ---------------------------------------------------------
extern "C" void kernel_launch(void* const* d_in, const int* in_sizes, int n_in,
                              void* d_out, int out_size) {
    const float* pt      = (const float*)d_in[0];
    const float* pc      = (const float*)d_in[1];
    const float* it      = (const float*)d_in[2];
    const float* icd     = (const float*)d_in[3];
    const int*   pvm     = (const int*)d_in[4];
    const int*   ivm     = (const int*)d_in[5];
    const float* ip_ln_g = (const float*)d_in[6];
    const float* ip_ln_b = (const float*)d_in[7];
    const float* ip_w1   = (const float*)d_in[8];
    const float* ip_b1   = (const float*)d_in[9];
    const float* ip_w2   = (const float*)d_in[10];
    const float* ip_b2   = (const float*)d_in[11];
    const float* g_ln_g  = (const float*)d_in[12];
    const float* g_ln_b  = (const float*)d_in[13];
    const float* g_w1    = (const float*)d_in[14];
    const float* g_b1    = (const float*)d_in[15];
    const float* g_w2    = (const float*)d_in[16];
    const float* g_b2    = (const float*)d_in[17];
    const float* d_ln_g  = (const float*)d_in[18];
    const float* d_ln_b  = (const float*)d_in[19];
    const float* d_w1    = (const float*)d_in[20];
    const float* d_b1    = (const float*)d_in[21];
    const float* d_w2    = (const float*)d_in[22];
    const float* d_b2    = (const float*)d_in[23];
    float* out = (float*)d_out;

    __half *xln, *hbuf, *finln, *wt_ip1, *wt_gd1, *wt_ip2, *wt_g2, *wt_d2;
    float *imgf, *gate, *knnw, *bpip, *bpgd;
    int* knni;
    cudaGetSymbolAddress((void**)&xln,    g_xln);
    cudaGetSymbolAddress((void**)&hbuf,   g_hbuf);
    cudaGetSymbolAddress((void**)&imgf,   g_imgfeat);
    cudaGetSymbolAddress((void**)&finln,  g_finln);
    cudaGetSymbolAddress((void**)&gate,   g_gate);
    cudaGetSymbolAddress((void**)&knni,   g_knn_idx);
    cudaGetSymbolAddress((void**)&knnw,   g_knn_w);
    cudaGetSymbolAddress((void**)&wt_ip1, g_wt_ip1);
    cudaGetSymbolAddress((void**)&wt_gd1, g_wt_gd1);
    cudaGetSymbolAddress((void**)&wt_ip2, g_wt_ip2);
    cudaGetSymbolAddress((void**)&wt_g2,  g_wt_g2);
    cudaGetSymbolAddress((void**)&wt_d2,  g_wt_d2);
    cudaGetSymbolAddress((void**)&bpip,   g_bp_ip);
    cudaGetSymbolAddress((void**)&bpgd,   g_bp_gd);

    cudaFuncSetAttribute(mma_gemm<0>, cudaFuncAttributeMaxDynamicSharedMemorySize, SM_TOTAL);
    cudaFuncSetAttribute(mma_gemm<1>, cudaFuncAttributeMaxDynamicSharedMemorySize, SM_TOTAL);
    cudaFuncSetAttribute(mma_gemm<2>, cudaFuncAttributeMaxDynamicSharedMemorySize, SM_TOTAL);

    // Launch order keeps ncu (-s 5 -c 1) on launch #5 = img L1 GEMM.
    fold_w1<<<(IDim * HDim + 255) / 256, 256>>>(ip_w1, ip_ln_g, wt_ip1, IDim, HDim);    // 0
    fold_b1<<<HDim / 64, 256>>>(ip_w1, ip_ln_b, ip_b1, bpip, IDim, HDim);               // 1
    transpose_k<<<(HDim * ODim + 255) / 256, 256>>>(ip_w2, wt_ip2, HDim, ODim);         // 2
    ln_img_kernel<<<ROWS_IMG, 256>>>(it, xln);                                          // 3
    fold_w1<<<(HDim * HDim + 255) / 256, 256>>>(g_w1, g_ln_g, wt_gd1, HDim, HDim);      // 4

    // 5: image MLP layer 1 (profiled launch)
    mma_gemm<1><<<dim3(HDim / 128, ROWS_IMG / 128), 256, SM_TOTAL>>>(
        xln, IDim, wt_ip1, bpip, hbuf, IDim, HDim, nullptr, nullptr, nullptr);
    // 6: image MLP layer 2
    mma_gemm<0><<<dim3(ODim / 128, ROWS_IMG / 128), 256, SM_TOTAL>>>(
        hbuf, HDim, wt_ip2, ip_b2, imgf, HDim, ODim, nullptr, nullptr, nullptr);

    // remaining prep (independent of image path)
    fold_w1<<<(HDim * HDim + 255) / 256, 256>>>(d_w1, d_ln_g, wt_gd1 + (size_t)HDim * HDim,
                                                HDim, HDim);                            // 7
    fold_b1<<<HDim / 64, 256>>>(g_w1, g_ln_b, g_b1, bpgd, HDim, HDim);                  // 8
    fold_b1<<<HDim / 64, 256>>>(d_w1, d_ln_b, d_b1, bpgd + HDim, HDim, HDim);           // 9
    transpose_k<<<(HDim * ODim + 255) / 256, 256>>>(g_w2, wt_g2, HDim, ODim);           // 10
    transpose_k<<<(HDim * ODim + 255) / 256, 256>>>(d_w2, wt_d2, HDim, ODim);           // 11

    knn_kernel<<<dim3(Bb, Nn / 256), 256>>>(pc, icd, ivm, knni, knnw);                  // 12
    fin_ln_kernel<<<ROWS_PT, 128>>>(pt, pvm, finln);                                    // 13

    // 14: fused gate|delta layer 1 -> hbuf [ROWS_PT, 1024] (gate cols 0..511, delta 512..1023)
    mma_gemm<1><<<dim3((2 * HDim) / 128, ROWS_PT / 128), 256, SM_TOTAL>>>(
        finln, 2 * ODim, wt_gd1, bpgd, hbuf, 2 * ODim, 2 * HDim, nullptr, nullptr, nullptr);

    // 15: gate layer 2 -> g_gate (fp32, pre-sigmoid)
    mma_gemm<0><<<dim3(ODim / 128, ROWS_PT / 128), 256, SM_TOTAL>>>(
        hbuf, 2 * HDim, wt_g2, g_b2, gate, HDim, ODim, nullptr, nullptr, nullptr);

    // 16: delta layer 2 + fused final combine
    mma_gemm<2><<<dim3(ODim / 128, ROWS_PT / 128), 256, SM_TOTAL>>>(
        hbuf + HDim, 2 * HDim, wt_d2, d_b2, out, HDim, ODim, gate, pt, pvm);
}

// round 9
// speedup vs baseline: 4.4652x; 1.0165x over previous
#include <cuda_runtime.h>
#include <cuda_fp16.h>
#include <math.h>
#include <stdint.h>

// Problem dims (fixed by the dataset)
#define Bb   16
#define Nn   4096
#define Mm   1024
#define IDim 768
#define HDim 512
#define ODim 256
#define ROWS_IMG (Bb*Mm)   // 16384
#define ROWS_PT  (Bb*Nn)   // 65536

// ---------------- scratch (device globals; no allocation allowed) -------------
__device__ __align__(16) __half g_xln[ROWS_IMG * IDim];          // LN img tokens (fp16, permuted)
__device__ __align__(16) __half g_hbuf[ROWS_PT * 2 * HDim];      // hidden (fp16, permuted; up to 1024 wide)
__device__ __align__(16) float g_imgfeat[ROWS_IMG * ODim];       // image MLP out (fp32 plain)
__device__ __align__(16) __half g_finln[ROWS_PT * (2 * ODim)];   // fin̂ (fp16, permuted)
__device__ __align__(16) float g_gate[ROWS_PT * ODim];           // gate pre-sigmoid (fp32)
__device__ int   g_knn_idx[ROWS_PT * 3];
__device__ float g_knn_w[ROWS_PT * 3];
// transposed (LN-folded) weights: [N,K] K-major, fp16, permuted
__device__ __align__(16) __half g_wt_ip1[HDim * IDim];
__device__ __align__(16) __half g_wt_gd1[(2 * HDim) * HDim];     // fused gate|delta layer-1
__device__ __align__(16) __half g_wt_ip2[ODim * HDim];
__device__ __align__(16) __half g_wt_g2[ODim * HDim];
__device__ __align__(16) __half g_wt_d2[ODim * HDim];
__device__ float g_bp_ip[HDim];
__device__ float g_bp_gd[2 * HDim];                              // fused gate|delta bias

// ---------------- helpers ------------------------------------------------------
// k-pair permutation inside each 16-wide k group: pair p=(k>>1)&7 goes to slot
// q = 2*(p&3) | (p>>2). A thread's fragment pairs (p, p+4) become adjacent 8B.
__device__ __host__ __forceinline__ int permk(int k) {
    int p = (k >> 1) & 7;
    int q = ((p & 3) << 1) | (p >> 2);
    return (k & ~15) | (q << 1) | (k & 1);
}
__device__ __forceinline__ float gelu_f(float x) {
    return 0.5f * x * (1.0f + erff(x * 0.70710678118654752f));
}
__device__ __forceinline__ float sigmoid_f(float x) {
    return 1.0f / (1.0f + __expf(-x));
}
__device__ __forceinline__ float2 block_reduce2(float s, float ss) {
    __shared__ float sh[64];
    int lane = threadIdx.x & 31, w = threadIdx.x >> 5;
#pragma unroll
    for (int o = 16; o; o >>= 1) {
        s  += __shfl_down_sync(0xffffffffu, s,  o);
        ss += __shfl_down_sync(0xffffffffu, ss, o);
    }
    if (lane == 0) { sh[w] = s; sh[32 + w] = ss; }
    __syncthreads();
    int nw = (blockDim.x + 31) >> 5;
    if (w == 0) {
        s  = (lane < nw) ? sh[lane]      : 0.0f;
        ss = (lane < nw) ? sh[32 + lane] : 0.0f;
#pragma unroll
        for (int o = 16; o; o >>= 1) {
            s  += __shfl_down_sync(0xffffffffu, s,  o);
            ss += __shfl_down_sync(0xffffffffu, ss, o);
        }
        if (lane == 0) { sh[0] = s; sh[32] = ss; }
    }
    __syncthreads();
    return make_float2(sh[0], sh[32]);
}

// ---------------- K0a: elementwise LN-gain fold + transpose (fp16, permuted) ----
__global__ void fold_w1(const float* __restrict__ W, const float* __restrict__ gain,
                        __half* __restrict__ Wt, int Kd, int Nc) {
    int idx = blockIdx.x * blockDim.x + threadIdx.x;
    if (idx >= Kd * Nc) return;
    int k = idx / Nc, n = idx % Nc;
    Wt[(size_t)n * Kd + permk(k)] = __float2half_rn(gain[k] * W[idx]);
}
// ---------------- K0b: bias fold: b1p[n] = b1[n] + sum_k bln[k]*W[k,n] -----------
__global__ void fold_b1(const float* __restrict__ W, const float* __restrict__ bln,
                        const float* __restrict__ b1, float* __restrict__ b1p,
                        int Kd, int Nc) {
    __shared__ float sh[256];
    int nl = threadIdx.x & 63, ks = threadIdx.x >> 6;
    int n = blockIdx.x * 64 + nl;
    float acc = 0.0f;
    for (int k = ks; k < Kd; k += 4)
        acc += bln[k] * W[(size_t)k * Nc + n];
    sh[threadIdx.x] = acc;
    __syncthreads();
    if (ks == 0)
        b1p[n] = b1[n] + sh[nl] + sh[64 + nl] + sh[128 + nl] + sh[192 + nl];
}
// ---------------- K0c: plain transpose (fp16, permuted) -------------------------
__global__ void transpose_k(const float* __restrict__ W, __half* __restrict__ Wt,
                            int Kd, int Nc) {
    int idx = blockIdx.x * blockDim.x + threadIdx.x;
    if (idx >= Kd * Nc) return;
    int k = idx / Nc, n = idx % Nc;
    Wt[(size_t)n * Kd + permk(k)] = __float2half_rn(W[idx]);
}

// ---------------- K1: LN (normalize only), fp16 permuted store ------------------
__global__ void ln_img_kernel(const float* __restrict__ x, __half* __restrict__ y) {
    int row = blockIdx.x, tid = threadIdx.x;
    const float* xr = x + (size_t)row * IDim;
    float v0 = xr[tid], v1 = xr[tid + 256], v2 = xr[tid + 512];
    float s = v0 + v1 + v2;
    float ss = v0 * v0 + v1 * v1 + v2 * v2;
    float2 r = block_reduce2(s, ss);
    float mean = r.x * (1.0f / 768.0f);
    float var  = fmaxf(r.y * (1.0f / 768.0f) - mean * mean, 0.0f);
    float rstd = rsqrtf(var + 1e-5f);
    __half* yr = y + (size_t)row * IDim;
    yr[permk(tid)]       = __float2half_rn((v0 - mean) * rstd);
    yr[permk(tid + 256)] = __float2half_rn((v1 - mean) * rstd);
    yr[permk(tid + 512)] = __float2half_rn((v2 - mean) * rstd);
}

// ---------------- K2: fp16 m16n8k16 mma.sync GEMM -------------------------------
// C[R,Nc] = A[R,Kd] @ Bt[Nc,Kd]^T; A row stride lda. 128x128 tile, KTILE=32,
// 4-stage cp.async, 2 CTAs/SM.
// ACT: 0 fp32 out, 1 gelu -> fp16 permuted out (hbuf), 2 final combine fp32 out.
#define KTILE   32
#define PITCHB  96                           // bytes/row: 64 data + 32 pad
#define TILE_B  (128 * PITCHB)               // 12288 bytes
#define STAGE_B (2 * TILE_B)                 // 24576
#define STAGES  4
#define SM_TOTAL (STAGES * STAGE_B)          // 98304 -> still 2 CTAs/SM

#define CPA_COMMIT() asm volatile("cp.async.commit_group;" ::: "memory")
#define CPA_WAIT2()  asm volatile("cp.async.wait_group 2;" ::: "memory")

__device__ __forceinline__ uint32_t smem_u32(const void* p) {
    uint32_t a;
    asm("{ .reg .u64 t; cvta.to.shared.u64 t, %1; cvt.u32.u64 %0, t; }" : "=r"(a) : "l"(p));
    return a;
}

// one 128x32(fp16) tile: 128 rows x 64B = 512 x 16B chunks, 2 per thread
__device__ __forceinline__ void load_tile(uint32_t sbase, const __half* gbase, int ld) {
    int t = threadIdx.x;
#pragma unroll
    for (int i = 0; i < 2; i++) {
        int idx = t + i * 256;
        int r = idx >> 2, c = idx & 3;
        uint32_t so = sbase + (uint32_t)(r * PITCHB + c * 16);
        const __half* gp = gbase + (size_t)r * ld + c * 8;
        asm volatile("cp.async.cg.shared.global [%0], [%1], 16;" :: "r"(so), "l"(gp));
    }
}

__device__ __forceinline__ void mma_f16(float* d, uint32_t a0, uint32_t a1, uint32_t a2,
                                        uint32_t a3, uint32_t b0, uint32_t b1) {
    asm volatile(
        "mma.sync.aligned.m16n8k16.row.col.f32.f16.f16.f32 "
        "{%0,%1,%2,%3}, {%4,%5,%6,%7}, {%8,%9}, {%0,%1,%2,%3};"
        : "+f"(d[0]), "+f"(d[1]), "+f"(d[2]), "+f"(d[3])
        : "r"(a0), "r"(a1), "r"(a2), "r"(a3), "r"(b0), "r"(b1));
}

template <int ACT>
__global__ __launch_bounds__(256, 2)
void mma_gemm(const __half* __restrict__ A, int lda, const __half* __restrict__ Bt,
              const float* __restrict__ bias, void* __restrict__ Cv,
              int Kd, int Nc,
              const float* __restrict__ gbuf, const float* __restrict__ ptb,
              const int* __restrict__ pvm) {
    extern __shared__ char smem[];
    uint32_t sb = smem_u32(smem);
    int tid = threadIdx.x, wid = tid >> 5, lane = tid & 31;
    int wm = wid & 1, wn = wid >> 1;              // 2x4 warp grid, warp tile 64x32
    int g = lane >> 2, i4 = lane & 3;
    int row0 = blockIdx.y * 128, col0 = blockIdx.x * 128;

    const int NK = Kd / KTILE;
    const __half* Ag = A  + (size_t)row0 * lda;
    const __half* Bg = Bt + (size_t)col0 * Kd;

    // prologue: stages 0,1,2
#pragma unroll
    for (int p = 0; p < 3; p++) {
        load_tile(sb + p * STAGE_B,          Ag + p * KTILE, lda);
        load_tile(sb + p * STAGE_B + TILE_B, Bg + p * KTILE, Kd);
        CPA_COMMIT();
    }

    float acc[4][4][4];
#pragma unroll
    for (int mf = 0; mf < 4; mf++)
#pragma unroll
        for (int nf = 0; nf < 4; nf++)
#pragma unroll
            for (int e = 0; e < 4; e++) acc[mf][nf][e] = 0.0f;

    for (int kt = 0; kt < NK; kt++) {
        CPA_WAIT2();                 // oldest outstanding group (tile kt) resident
        __syncthreads();             // stage (kt+3)%4 == (kt-1)%4 fully consumed
        if (kt + 3 < NK) {
            int st = (kt + 3) % STAGES;
            load_tile(sb + st * STAGE_B,          Ag + (size_t)(kt + 3) * KTILE, lda);
            load_tile(sb + st * STAGE_B + TILE_B, Bg + (size_t)(kt + 3) * KTILE, Kd);
        }
        CPA_COMMIT();

        int s = kt % STAGES;
        const char* As = smem + s * STAGE_B;
        const char* Bs = smem + s * STAGE_B + TILE_B;
#pragma unroll
        for (int ks = 0; ks < 2; ks++) {
            int kb = ks * 32 + 8 * i4;            // byte offset: thread's adjacent pair group
            uint2 alo[4], ahi[4], bf[4];
#pragma unroll
            for (int mf = 0; mf < 4; mf++) {
                const char* base = As + (wm * 64 + mf * 16 + g) * PITCHB + kb;
                alo[mf] = *(const uint2*)base;                  // row g:   (a0, a2)
                ahi[mf] = *(const uint2*)(base + 8 * PITCHB);   // row g+8: (a1, a3)
            }
#pragma unroll
            for (int nf = 0; nf < 4; nf++)
                bf[nf] = *(const uint2*)(Bs + (wn * 32 + nf * 8 + g) * PITCHB + kb);
#pragma unroll
            for (int mf = 0; mf < 4; mf++)
#pragma unroll
                for (int nf = 0; nf < 4; nf++)
                    mma_f16(acc[mf][nf],
                            alo[mf].x, ahi[mf].x, alo[mf].y, ahi[mf].y,
                            bf[nf].x,  bf[nf].y);
        }
    }

    // epilogue
#pragma unroll
    for (int mf = 0; mf < 4; mf++) {
        int r_lo = row0 + wm * 64 + mf * 16 + g;
#pragma unroll
        for (int nf = 0; nf < 4; nf++) {
            int col = col0 + wn * 32 + nf * 8 + i4 * 2;
            float b0 = bias[col], b1 = bias[col + 1];
#pragma unroll
            for (int h = 0; h < 2; h++) {
                int row = r_lo + h * 8;
                float v0 = acc[mf][nf][h * 2 + 0] + b0;
                float v1 = acc[mf][nf][h * 2 + 1] + b1;
                if (ACT == 1) {
                    // gelu -> fp16 permuted store (hbuf is next GEMM's A)
                    __half2 o;
                    o.x = __float2half_rn(gelu_f(v0));
                    o.y = __float2half_rn(gelu_f(v1));
                    __half* C = (__half*)Cv;
                    *(__half2*)(C + (size_t)row * Nc + permk(col)) = o;
                } else {
                    float* C = (float*)Cv;
                    size_t off = (size_t)row * Nc + col;
                    if (ACT == 2) {
                        float2 g4 = *(const float2*)(gbuf + off);
                        float2 p4 = *(const float2*)(ptb + off);
                        float m = pvm[row] ? 1.0f : 0.0f;
                        v0 = (p4.x + sigmoid_f(g4.x) * v0) * m;
                        v1 = (p4.y + sigmoid_f(g4.y) * v1) * m;
                    }
                    *(float2*)(C + off) = make_float2(v0, v1);
                }
            }
        }
    }
}

// ---------------- K3: kNN top-3 + inverse-distance weights ----------------------
__global__ __launch_bounds__(256)
void knn_kernel(const float* __restrict__ pc, const float* __restrict__ ic,
                const int* __restrict__ imask,
                int* __restrict__ knn_idx, float* __restrict__ knn_w) {
    __shared__ float4 cs[Mm];
    int b = blockIdx.x;
    const float INFV = __int_as_float(0x7f800000);
    for (int m = threadIdx.x; m < Mm; m += 256) {
        size_t ci = ((size_t)b * Mm + m) * 3;
        float x = ic[ci], y = ic[ci + 1], z = ic[ci + 2];
        float s2 = imask[b * Mm + m] ? (x * x + y * y + z * z) : INFV;
        cs[m] = make_float4(x, y, z, s2);
    }
    __syncthreads();

    int n = blockIdx.y * 256 + threadIdx.x;
    size_t pidx = (size_t)b * Nn + n;
    float qx = pc[pidx * 3], qy = pc[pidx * 3 + 1], qz = pc[pidx * 3 + 2];
    float q2 = qx * qx + qy * qy + qz * qz;

    float d0 = INFV, d1 = INFV, d2v = INFV;
    int j0 = 0, j1 = 0, j2 = 0;
#pragma unroll 4
    for (int m = 0; m < Mm; m++) {
        float4 c = cs[m];
        float d = fmaxf(q2 + c.w - 2.0f * (qx * c.x + qy * c.y + qz * c.z), 0.0f);
        if (d < d2v) {
            if (d < d1) {
                d2v = d1; j2 = j1;
                if (d < d0) { d1 = d0; j1 = j0; d0 = d; j0 = m; }
                else        { d1 = d;  j1 = m; }
            } else { d2v = d; j2 = m; }
        }
    }
    float w0 = 1.0f / fmaxf(sqrtf(d0),  1e-6f);
    float w1 = 1.0f / fmaxf(sqrtf(d1),  1e-6f);
    float w2 = 1.0f / fmaxf(sqrtf(d2v), 1e-6f);
    float inv = 1.0f / fmaxf(w0 + w1 + w2, 1e-6f);
    size_t base = pidx * 3;
    knn_idx[base + 0] = b * Mm + j0;
    knn_idx[base + 1] = b * Mm + j1;
    knn_idx[base + 2] = b * Mm + j2;
    knn_w[base + 0] = w0 * inv;
    knn_w[base + 1] = w1 * inv;
    knn_w[base + 2] = w2 * inv;
}

// ---------------- K4: gather + concat + LN, fp16 permuted store -----------------
__global__ __launch_bounds__(128)
void fin_ln_kernel(const float* __restrict__ pt, const int* __restrict__ pvm,
                   __half* __restrict__ out) {
    int p = blockIdx.x, tid = threadIdx.x;
    float4 v;
    if (tid < 64) {
        v = *(const float4*)&pt[(size_t)p * ODim + tid * 4];
    } else {
        int base = p * 3;
        int i0 = g_knn_idx[base], i1 = g_knn_idx[base + 1], i2 = g_knn_idx[base + 2];
        float w0 = g_knn_w[base], w1 = g_knn_w[base + 1], w2 = g_knn_w[base + 2];
        int o = (tid - 64) * 4;
        float4 f0 = *(const float4*)&g_imgfeat[(size_t)i0 * ODim + o];
        float4 f1 = *(const float4*)&g_imgfeat[(size_t)i1 * ODim + o];
        float4 f2 = *(const float4*)&g_imgfeat[(size_t)i2 * ODim + o];
        float pv = pvm[p] ? 1.0f : 0.0f;
        v.x = (w0 * f0.x + w1 * f1.x + w2 * f2.x) * pv;
        v.y = (w0 * f0.y + w1 * f1.y + w2 * f2.y) * pv;
        v.z = (w0 * f0.z + w1 * f1.z + w2 * f2.z) * pv;
        v.w = (w0 * f0.w + w1 * f1.w + w2 * f2.w) * pv;
    }
    float s  = v.x + v.y + v.z + v.w;
    float ss = v.x * v.x + v.y * v.y + v.z * v.z + v.w * v.w;
    float2 r = block_reduce2(s, ss);
    float mean = r.x * (1.0f / 512.0f);
    float var  = fmaxf(r.y * (1.0f / 512.0f) - mean * mean, 0.0f);
    float rstd = rsqrtf(var + 1e-5f);
    __half* orow = out + (size_t)p * 512;
    int c = tid * 4;
    __half2 o01, o23;
    o01.x = __float2half_rn((v.x - mean) * rstd);
    o01.y = __float2half_rn((v.y - mean) * rstd);
    o23.x = __float2half_rn((v.z - mean) * rstd);
    o23.y = __float2half_rn((v.w - mean) * rstd);
    *(__half2*)(orow + permk(c))     = o01;
    *(__half2*)(orow + permk(c + 2)) = o23;
}

// ---------------- launch ---------------------------------------------------------
extern "C" void kernel_launch(void* const* d_in, const int* in_sizes, int n_in,
                              void* d_out, int out_size) {
    const float* pt      = (const float*)d_in[0];
    const float* pc      = (const float*)d_in[1];
    const float* it      = (const float*)d_in[2];
    const float* icd     = (const float*)d_in[3];
    const int*   pvm     = (const int*)d_in[4];
    const int*   ivm     = (const int*)d_in[5];
    const float* ip_ln_g = (const float*)d_in[6];
    const float* ip_ln_b = (const float*)d_in[7];
    const float* ip_w1   = (const float*)d_in[8];
    const float* ip_b1   = (const float*)d_in[9];
    const float* ip_w2   = (const float*)d_in[10];
    const float* ip_b2   = (const float*)d_in[11];
    const float* g_ln_g  = (const float*)d_in[12];
    const float* g_ln_b  = (const float*)d_in[13];
    const float* g_w1    = (const float*)d_in[14];
    const float* g_b1    = (const float*)d_in[15];
    const float* g_w2    = (const float*)d_in[16];
    const float* g_b2    = (const float*)d_in[17];
    const float* d_ln_g  = (const float*)d_in[18];
    const float* d_ln_b  = (const float*)d_in[19];
    const float* d_w1    = (const float*)d_in[20];
    const float* d_b1    = (const float*)d_in[21];
    const float* d_w2    = (const float*)d_in[22];
    const float* d_b2    = (const float*)d_in[23];
    float* out = (float*)d_out;

    __half *xln, *hbuf, *finln, *wt_ip1, *wt_gd1, *wt_ip2, *wt_g2, *wt_d2;
    float *imgf, *gate, *knnw, *bpip, *bpgd;
    int* knni;
    cudaGetSymbolAddress((void**)&xln,    g_xln);
    cudaGetSymbolAddress((void**)&hbuf,   g_hbuf);
    cudaGetSymbolAddress((void**)&imgf,   g_imgfeat);
    cudaGetSymbolAddress((void**)&finln,  g_finln);
    cudaGetSymbolAddress((void**)&gate,   g_gate);
    cudaGetSymbolAddress((void**)&knni,   g_knn_idx);
    cudaGetSymbolAddress((void**)&knnw,   g_knn_w);
    cudaGetSymbolAddress((void**)&wt_ip1, g_wt_ip1);
    cudaGetSymbolAddress((void**)&wt_gd1, g_wt_gd1);
    cudaGetSymbolAddress((void**)&wt_ip2, g_wt_ip2);
    cudaGetSymbolAddress((void**)&wt_g2,  g_wt_g2);
    cudaGetSymbolAddress((void**)&wt_d2,  g_wt_d2);
    cudaGetSymbolAddress((void**)&bpip,   g_bp_ip);
    cudaGetSymbolAddress((void**)&bpgd,   g_bp_gd);

    cudaFuncSetAttribute(mma_gemm<0>, cudaFuncAttributeMaxDynamicSharedMemorySize, SM_TOTAL);
    cudaFuncSetAttribute(mma_gemm<1>, cudaFuncAttributeMaxDynamicSharedMemorySize, SM_TOTAL);
    cudaFuncSetAttribute(mma_gemm<2>, cudaFuncAttributeMaxDynamicSharedMemorySize, SM_TOTAL);

    // ncu captures 0-based launch index 3 -> put the img L1 GEMM there.
    fold_w1<<<(IDim * HDim + 255) / 256, 256>>>(ip_w1, ip_ln_g, wt_ip1, IDim, HDim);    // 0
    fold_b1<<<HDim / 64, 256>>>(ip_w1, ip_ln_b, ip_b1, bpip, IDim, HDim);               // 1
    ln_img_kernel<<<ROWS_IMG, 256>>>(it, xln);                                          // 2

    // 3: image MLP layer 1 (PROFILED launch)
    mma_gemm<1><<<dim3(HDim / 128, ROWS_IMG / 128), 256, SM_TOTAL>>>(
        xln, IDim, wt_ip1, bpip, hbuf, IDim, HDim, nullptr, nullptr, nullptr);

    transpose_k<<<(HDim * ODim + 255) / 256, 256>>>(ip_w2, wt_ip2, HDim, ODim);         // 4
    // 5: image MLP layer 2
    mma_gemm<0><<<dim3(ODim / 128, ROWS_IMG / 128), 256, SM_TOTAL>>>(
        hbuf, HDim, wt_ip2, ip_b2, imgf, HDim, ODim, nullptr, nullptr, nullptr);

    // remaining prep (independent of image path)
    fold_w1<<<(HDim * HDim + 255) / 256, 256>>>(g_w1, g_ln_g, wt_gd1, HDim, HDim);      // 6
    fold_w1<<<(HDim * HDim + 255) / 256, 256>>>(d_w1, d_ln_g, wt_gd1 + (size_t)HDim * HDim,
                                                HDim, HDim);                            // 7
    fold_b1<<<HDim / 64, 256>>>(g_w1, g_ln_b, g_b1, bpgd, HDim, HDim);                  // 8
    fold_b1<<<HDim / 64, 256>>>(d_w1, d_ln_b, d_b1, bpgd + HDim, HDim, HDim);           // 9
    transpose_k<<<(HDim * ODim + 255) / 256, 256>>>(g_w2, wt_g2, HDim, ODim);           // 10
    transpose_k<<<(HDim * ODim + 255) / 256, 256>>>(d_w2, wt_d2, HDim, ODim);           // 11

    knn_kernel<<<dim3(Bb, Nn / 256), 256>>>(pc, icd, ivm, knni, knnw);                  // 12
    fin_ln_kernel<<<ROWS_PT, 128>>>(pt, pvm, finln);                                    // 13

    // 14: fused gate|delta layer 1 -> hbuf [ROWS_PT, 1024]
    mma_gemm<1><<<dim3((2 * HDim) / 128, ROWS_PT / 128), 256, SM_TOTAL>>>(
        finln, 2 * ODim, wt_gd1, bpgd, hbuf, 2 * ODim, 2 * HDim, nullptr, nullptr, nullptr);

    // 15: gate layer 2 -> g_gate (fp32, pre-sigmoid)
    mma_gemm<0><<<dim3(ODim / 128, ROWS_PT / 128), 256, SM_TOTAL>>>(
        hbuf, 2 * HDim, wt_g2, g_b2, gate, HDim, ODim, nullptr, nullptr, nullptr);

    // 16: delta layer 2 + fused final combine
    mma_gemm<2><<<dim3(ODim / 128, ROWS_PT / 128), 256, SM_TOTAL>>>(
        hbuf + HDim, 2 * HDim, wt_d2, d_b2, out, HDim, ODim, gate, pt, pvm);
}